// round 6
// baseline (speedup 1.0000x reference)
#include <cuda_runtime.h>
#include <cuda_bf16.h>
#include <cstdint>
#include <math.h>

// Problem constants
#define Bb   8
#define Cc   1536
#define Tt   4096
#define Aa   128
#define K3C  4608          // 3*C
#define EPSF 1e-12f

// ---------------- scratch (device globals; no allocation allowed) ----------------
__device__ __nv_bfloat16 g_xh[(size_t)Bb * Cc * Tt];   // x hi (96MB)
__device__ __nv_bfloat16 g_xl[(size_t)Bb * Cc * Tt];
__device__ __nv_bfloat16 g_mh[(size_t)Bb * Cc * Tt];   // mean hi
__device__ __nv_bfloat16 g_ml[(size_t)Bb * Cc * Tt];
__device__ __nv_bfloat16 g_sh[(size_t)Bb * Cc * Tt];   // std hi
__device__ __nv_bfloat16 g_sl[(size_t)Bb * Cc * Tt];
__device__ __nv_bfloat16 g_W1h[Aa * K3C];
__device__ __nv_bfloat16 g_W1l[Aa * K3C];
__device__ float g_logits[Bb * Tt];
__device__ float g_e     [Bb * Tt];
__device__ float g_Z     [Bb * Tt];

// ---------------- helpers ----------------
__device__ __forceinline__ uint32_t smem_u32(const void* p) {
    uint32_t a;
    asm("{ .reg .u64 t; cvta.to.shared.u64 t, %1; cvt.u32.u64 %0, t; }" : "=r"(a) : "l"(p));
    return a;
}
__device__ __forceinline__ int load_len(const int* __restrict__ L, int b) {
    return (L[1] == 0) ? L[2 * b] : L[b];   // int64 vs int32 detection
}
__device__ __forceinline__ void split_bf16(float v, __nv_bfloat16& h, __nv_bfloat16& l) {
    h = __float2bfloat16_rn(v);
    l = __float2bfloat16_rn(v - __bfloat162float(h));
}
__device__ __forceinline__ float fast_tanh(float v) {
    float e = __expf(2.f * v);          // inf-safe: e=inf -> 1, e=0 -> -1
    return 1.f - 2.f / (e + 1.f);
}
__device__ __forceinline__ float warp_iscan(float v, int lane) {
    #pragma unroll
    for (int off = 1; off < 32; off <<= 1) {
        float n = __shfl_up_sync(0xFFFFFFFFu, v, off);
        if (lane >= off) v += n;
    }
    return v;
}
// block-wide (256 thr) EXCLUSIVE scan of two values; 2 barriers.
__device__ __forceinline__ void block_exscan2(float& v1, float& v2, int tid,
                                              float* ws1, float* ws2) {
    int lane = tid & 31, wid = tid >> 5;
    float o1 = v1, o2 = v2;
    float i1 = warp_iscan(o1, lane), i2 = warp_iscan(o2, lane);
    if (lane == 31) { ws1[wid] = i1; ws2[wid] = i2; }
    __syncthreads();
    if (wid == 0) {
        float a1 = (lane < 8) ? ws1[lane] : 0.f;
        float a2 = (lane < 8) ? ws2[lane] : 0.f;
        float c1 = warp_iscan(a1, lane), c2 = warp_iscan(a2, lane);
        if (lane < 8) { ws1[lane] = c1; ws2[lane] = c2; }
    }
    __syncthreads();
    float p1 = wid ? ws1[wid - 1] : 0.f;
    float p2 = wid ? ws2[wid - 1] : 0.f;
    v1 = p1 + i1 - o1;
    v2 = p2 + i2 - o2;
}
__device__ __forceinline__ float block_exscan1(float v, int tid, float* ws) {
    int lane = tid & 31, wid = tid >> 5;
    float o = v;
    float i = warp_iscan(o, lane);
    if (lane == 31) ws[wid] = i;
    __syncthreads();
    if (wid == 0) {
        float a = (lane < 8) ? ws[lane] : 0.f;
        float c = warp_iscan(a, lane);
        if (lane < 8) ws[lane] = c;
    }
    __syncthreads();
    float p = wid ? ws[wid - 1] : 0.f;
    return p + i - o;
}

// ldmatrix / mma wrappers
__device__ __forceinline__ void ldsm_x4(uint32_t& r0, uint32_t& r1, uint32_t& r2, uint32_t& r3, uint32_t a) {
    asm volatile("ldmatrix.sync.aligned.m8n8.x4.shared.b16 {%0,%1,%2,%3}, [%4];"
                 : "=r"(r0), "=r"(r1), "=r"(r2), "=r"(r3) : "r"(a));
}
__device__ __forceinline__ void ldsm_x4_t(uint32_t& r0, uint32_t& r1, uint32_t& r2, uint32_t& r3, uint32_t a) {
    asm volatile("ldmatrix.sync.aligned.m8n8.x4.trans.shared.b16 {%0,%1,%2,%3}, [%4];"
                 : "=r"(r0), "=r"(r1), "=r"(r2), "=r"(r3) : "r"(a));
}
__device__ __forceinline__ void mma_bf16(float* d, const uint32_t* a, const uint32_t* b) {
    asm volatile(
        "mma.sync.aligned.m16n8k16.row.col.f32.bf16.bf16.f32 "
        "{%0,%1,%2,%3},{%4,%5,%6,%7},{%8,%9},{%0,%1,%2,%3};"
        : "+f"(d[0]), "+f"(d[1]), "+f"(d[2]), "+f"(d[3])
        : "r"(a[0]), "r"(a[1]), "r"(a[2]), "r"(a[3]), "r"(b[0]), "r"(b[1]));
}
__device__ __forceinline__ void cpa_cg(uint32_t dst, const void* src) {
    asm volatile("cp.async.cg.shared.global [%0], [%1], 16;" :: "r"(dst), "l"(src));
}
__device__ __forceinline__ void cpa_ca(uint32_t dst, const void* src) {
    asm volatile("cp.async.ca.shared.global [%0], [%1], 16;" :: "r"(dst), "l"(src));
}

// ---------------- K0: W1 -> bf16 hi/lo ----------------
__global__ __launch_bounds__(256) void k_prepW(const float* __restrict__ W1) {
    int i = blockIdx.x * 256 + threadIdx.x;
    if (i < Aa * K3C) {
        __nv_bfloat16 h, l;
        split_bf16(W1[i], h, l);
        g_W1h[i] = h; g_W1l[i] = l;
    }
}

// ---------------- K1: x -> bf16 hi/lo + causal mean/std -> bf16 hi/lo ----------------
__global__ __launch_bounds__(256) void k_scan_stats(const float* __restrict__ x,
                                                    const int* __restrict__ L) {
    int row = blockIdx.x;               // b*C + c
    int b = row / Cc;
    int len = load_len(L, b);

    __shared__ float xs[Tt];
    __shared__ float ss[Tt];
    __shared__ float ws1[8], ws2[8];

    int tid = threadIdx.x;
    const float* xr = x + (size_t)row * Tt;
    for (int j = tid; j < Tt; j += 256) xs[j] = xr[j];
    __syncthreads();

    size_t gb = (size_t)row * Tt;
    // write xh/xl, 8 bf16 packed per 16B store
    for (int g = tid; g < Tt / 8; g += 256) {
        int base = g * 8;
        uint4 ph, pl;
        unsigned short* hp = (unsigned short*)&ph;
        unsigned short* lp = (unsigned short*)&pl;
        #pragma unroll
        for (int k = 0; k < 8; k++) {
            __nv_bfloat16 h, l;
            split_bf16(xs[base + k], h, l);
            hp[k] = __bfloat16_as_ushort(h); lp[k] = __bfloat16_as_ushort(l);
        }
        *(uint4*)(g_xh + gb + base) = ph;
        *(uint4*)(g_xl + gb + base) = pl;
    }

    int base = tid * 16;
    float s1 = 0.f, s2 = 0.f;
    #pragma unroll
    for (int k = 0; k < 16; k++) {
        int t = base + k;
        float v = (t < len) ? xs[t] : 0.f;
        s1 += v; s2 += v * v;
    }
    // exclusive prefixes (internal barriers also fence the xh/xl reads above)
    block_exscan2(s1, s2, tid, ws1, ws2);

    float p1 = s1, p2 = s2;
    #pragma unroll
    for (int k = 0; k < 16; k++) {
        int t = base + k;
        float xv = xs[t];
        float v  = (t < len) ? xv : 0.f;
        p1 += v; p2 += v * v;
        int cn = min(t + 1, len); if (cn < 1) cn = 1;
        float cnf = (float)cn;
        float m   = p1 / cnf;
        float var = p2 / cnf - m * m;
        xs[t] = m;
        ss[t] = sqrtf(fmaxf(var, EPSF));
    }
    __syncthreads();

    for (int g = tid; g < Tt / 8; g += 256) {
        int bb = g * 8;
        uint4 mh, ml, sh, sl;
        unsigned short* mhp = (unsigned short*)&mh; unsigned short* mlp = (unsigned short*)&ml;
        unsigned short* shp = (unsigned short*)&sh; unsigned short* slp = (unsigned short*)&sl;
        #pragma unroll
        for (int k = 0; k < 8; k++) {
            __nv_bfloat16 h, l;
            split_bf16(xs[bb + k], h, l); mhp[k] = __bfloat16_as_ushort(h); mlp[k] = __bfloat16_as_ushort(l);
            split_bf16(ss[bb + k], h, l); shp[k] = __bfloat16_as_ushort(h); slp[k] = __bfloat16_as_ushort(l);
        }
        *(uint4*)(g_mh + gb + bb) = mh; *(uint4*)(g_ml + gb + bb) = ml;
        *(uint4*)(g_sh + gb + bb) = sh; *(uint4*)(g_sl + gb + bb) = sl;
    }
}

// ---------------- K2: pipelined bf16 mma.sync GEMM + tanh + W2 reduce -> logits ----------------
#define BM 128
#define BK 32
#define NK (K3C / BK)        // 144
#define APITCH 272           // bytes per k-row (128 t * 2B + 16 pad)
#define BPITCH 80            // bytes per a-row (32 k * 2B + 16 pad)
#define OFF_AL 8704
#define OFF_BH 17408
#define OFF_BL 27648
#define SSTR   37888         // one stage: Ah+Al+Bh+Bl
#define NSTAGE 3
#define OFF_RED (NSTAGE * SSTR)
#define SMEM_GEMM (OFF_RED + 2 * BM * 4)    // 114688 B

__device__ __forceinline__ void gemm_load_tile(int j, uint32_t st, int b, int t0, int tid) {
    int k0 = j * BK;
    int region = k0 / Cc;                // 0:x 1:mean 2:std (BK=32 never straddles)
    int cb = k0 - region * Cc;
    const __nv_bfloat16* pH = (region == 0 ? g_xh : (region == 1 ? g_mh : g_sh))
                              + ((size_t)(b * Cc + cb)) * Tt + t0;
    const __nv_bfloat16* pL = (region == 0 ? g_xl : (region == 1 ? g_ml : g_sl))
                              + ((size_t)(b * Cc + cb)) * Tt + t0;
    #pragma unroll
    for (int p = 0; p < 2; p++) {
        int id = tid + p * 256;          // 0..511
        int r  = id >> 4, c = id & 15;   // A: 32 rows x 16 chunks(16B)
        cpa_cg(st + r * APITCH + c * 16,          pH + (size_t)r * Tt + c * 8);
        cpa_cg(st + OFF_AL + r * APITCH + c * 16, pL + (size_t)r * Tt + c * 8);
        int rb = id >> 2, cc = id & 3;   // B: 128 rows x 4 chunks(16B)
        cpa_ca(st + OFF_BH + rb * BPITCH + cc * 16, g_W1h + (size_t)rb * K3C + k0 + cc * 8);
        cpa_ca(st + OFF_BL + rb * BPITCH + cc * 16, g_W1l + (size_t)rb * K3C + k0 + cc * 8);
    }
}

__global__ __launch_bounds__(256, 2) void k_gemm_mma(const float* __restrict__ b1,
                                                     const float* __restrict__ W2) {
    extern __shared__ __align__(16) char dsm[];
    uint32_t sb = smem_u32(dsm);

    int tid = threadIdx.x;
    int wid = tid >> 5, lid = tid & 31;
    int wm = wid & 3;          // 4 m-warps * 32 t
    int wn = wid >> 2;         // 2 n-warps * 64 a
    int b  = blockIdx.y, t0 = blockIdx.x * BM;

    // ldmatrix lane addressing
    int a_row_off = (lid & 7) + ((lid >> 4) << 3);
    int a_t_off   = wm * 32 + ((lid >> 3) & 1) * 8;
    int b_row     = wn * 64 + (lid & 7) + ((lid >> 4) << 3);
    int b_k_off   = ((lid >> 3) & 1) * 8;

    float acc[2][8][4];
    #pragma unroll
    for (int i = 0; i < 2; i++)
        #pragma unroll
        for (int j = 0; j < 8; j++)
            #pragma unroll
            for (int q = 0; q < 4; q++) acc[i][j][q] = 0.f;

    gemm_load_tile(0, sb, b, t0, tid);
    asm volatile("cp.async.commit_group;" ::: "memory");
    gemm_load_tile(1, sb + SSTR, b, t0, tid);
    asm volatile("cp.async.commit_group;" ::: "memory");

    for (int it = 0; it < NK; it++) {
        if (it + 2 < NK)
            gemm_load_tile(it + 2, sb + ((it + 2) % NSTAGE) * SSTR, b, t0, tid);
        asm volatile("cp.async.commit_group;" ::: "memory");
        asm volatile("cp.async.wait_group 2;" ::: "memory");
        __syncthreads();

        uint32_t stb = sb + (it % NSTAGE) * SSTR;
        uint32_t uAh = stb, uAl = stb + OFF_AL, uBh = stb + OFF_BH, uBl = stb + OFF_BL;

        #pragma unroll
        for (int s = 0; s < 2; s++) {                 // two k16 steps
            uint32_t ah[2][4], al[2][4];
            #pragma unroll
            for (int mf = 0; mf < 2; mf++) {
                uint32_t addr = (s * 16 + a_row_off) * APITCH + (a_t_off + mf * 16) * 2;
                ldsm_x4_t(ah[mf][0], ah[mf][1], ah[mf][2], ah[mf][3], uAh + addr);
                ldsm_x4_t(al[mf][0], al[mf][1], al[mf][2], al[mf][3], uAl + addr);
            }
            #pragma unroll
            for (int nb2 = 0; nb2 < 4; nb2++) {       // 4 groups of 16 a
                uint32_t addr = (b_row + nb2 * 16) * BPITCH + (s * 16 + b_k_off) * 2;
                uint32_t bh[4], bl[4];
                ldsm_x4(bh[0], bh[1], bh[2], bh[3], uBh + addr);
                ldsm_x4(bl[0], bl[1], bl[2], bl[3], uBl + addr);
                #pragma unroll
                for (int half = 0; half < 2; half++) {
                    int nb = nb2 * 2 + half;
                    #pragma unroll
                    for (int mf = 0; mf < 2; mf++) {
                        mma_bf16(acc[mf][nb], ah[mf], bh + half * 2);
                        mma_bf16(acc[mf][nb], al[mf], bh + half * 2);
                        mma_bf16(acc[mf][nb], ah[mf], bl + half * 2);
                    }
                }
            }
        }
        __syncthreads();
    }

    // ---- epilogue: h = tanh(acc + b1[a]); row-sum of W2[a]*h over a ----
    float* red = (float*)(dsm + OFF_RED);   // [2][BM]
    float rs[2][2] = {{0.f, 0.f}, {0.f, 0.f}};
    #pragma unroll
    for (int nb = 0; nb < 8; nb++) {
        int a0 = wn * 64 + nb * 8 + (lid & 3) * 2;
        float w20 = __ldg(&W2[a0]),   w21 = __ldg(&W2[a0 + 1]);
        float b10 = __ldg(&b1[a0]),   b11 = __ldg(&b1[a0 + 1]);
        #pragma unroll
        for (int mf = 0; mf < 2; mf++) {
            rs[mf][0] += w20 * fast_tanh(acc[mf][nb][0] + b10)
                       + w21 * fast_tanh(acc[mf][nb][1] + b11);
            rs[mf][1] += w20 * fast_tanh(acc[mf][nb][2] + b10)
                       + w21 * fast_tanh(acc[mf][nb][3] + b11);
        }
    }
    #pragma unroll
    for (int mf = 0; mf < 2; mf++)
        #pragma unroll
        for (int r = 0; r < 2; r++) {
            rs[mf][r] += __shfl_xor_sync(0xFFFFFFFF, rs[mf][r], 1);
            rs[mf][r] += __shfl_xor_sync(0xFFFFFFFF, rs[mf][r], 2);
        }
    if ((lid & 3) == 0) {
        int trow = wm * 32 + (lid >> 2);
        #pragma unroll
        for (int mf = 0; mf < 2; mf++) {
            red[wn * BM + trow + mf * 16]     = rs[mf][0];
            red[wn * BM + trow + mf * 16 + 8] = rs[mf][1];
        }
    }
    __syncthreads();
    if (tid < BM)
        g_logits[b * Tt + t0 + tid] = red[tid] + red[BM + tid];
}

// ---------------- K3: per-batch max, exp, cumsum -> e, Z ----------------
__global__ __launch_bounds__(256) void k_softmax() {
    int b = blockIdx.x;
    __shared__ float sm[Tt];
    __shared__ float red[256];
    __shared__ float ws[8];
    int tid = threadIdx.x;

    const float* lr = g_logits + b * Tt;
    float mx = -INFINITY;
    for (int j = tid; j < Tt; j += 256) { float v = lr[j]; sm[j] = v; mx = fmaxf(mx, v); }
    red[tid] = mx;
    __syncthreads();
    for (int off = 128; off; off >>= 1) {
        if (tid < off) red[tid] = fmaxf(red[tid], red[tid + off]);
        __syncthreads();
    }
    float M = red[0];
    __syncthreads();

    int base = tid * 16;
    float s = 0.f;
    #pragma unroll
    for (int k = 0; k < 16; k++) {
        float ev = expf(sm[base + k] - M);
        sm[base + k] = ev;
        s += ev;
    }
    float p = block_exscan1(s, tid, ws);
    #pragma unroll
    for (int k = 0; k < 16; k++) {
        int t = base + k;
        float ev = sm[t];
        p += ev;
        g_e[b * Tt + t] = ev;
        g_Z[b * Tt + t] = p;
    }
}

// ---------------- K4: weighted mean/std scans + final reduction ----------------
__global__ __launch_bounds__(256) void k_weighted(const float* __restrict__ x,
                                                  float* __restrict__ out) {
    int row = blockIdx.x;
    int b = row / Cc;
    int c = row - b * Cc;

    __shared__ float xs[Tt];
    __shared__ float es[Tt];
    __shared__ float ws[8];
    __shared__ float w1s[256], w2s[256];

    int tid = threadIdx.x;
    const float* xr = x + (size_t)row * Tt;
    const float* er = g_e + b * Tt;
    const float* zr = g_Z + b * Tt;
    for (int j = tid; j < Tt; j += 256) { xs[j] = xr[j]; es[j] = er[j]; }
    __syncthreads();

    int base = tid * 16;

    float s = 0.f;
    #pragma unroll
    for (int k = 0; k < 16; k++) { int t = base + k; s += es[t] * xs[t]; }
    float p = block_exscan1(s, tid, ws);

    float sum_wm = 0.f, s2 = 0.f;
    #pragma unroll
    for (int k = 0; k < 16; k++) {
        int t = base + k;
        p += es[t] * xs[t];
        float wm = p / zr[t];
        sum_wm += wm;
        float d = xs[t] - wm;
        float v = es[t] * d * d;
        xs[t] = v;
        s2 += v;
    }
    __syncthreads();   // ws reuse fence

    float q = block_exscan1(s2, tid, ws);
    float sum_ws = 0.f;
    #pragma unroll
    for (int k = 0; k < 16; k++) {
        int t = base + k;
        q += xs[t];
        float wv = q / zr[t];
        sum_ws += sqrtf(fmaxf(wv, EPSF));
    }
    __syncthreads();

    w1s[tid] = sum_wm;
    w2s[tid] = sum_ws;
    __syncthreads();
    for (int off = 128; off; off >>= 1) {
        if (tid < off) { w1s[tid] += w1s[tid + off]; w2s[tid] += w2s[tid + off]; }
        __syncthreads();
    }
    if (tid == 0) {
        const float FW = (float)(1.0 / (4096.0 + 1e-12));
        out[(size_t)b * 2 * Cc + c]      = w1s[0] * FW;
        out[(size_t)b * 2 * Cc + Cc + c] = w2s[0] * FW;
    }
}

// ---------------- launch ----------------
extern "C" void kernel_launch(void* const* d_in, const int* in_sizes, int n_in,
                              void* d_out, int out_size) {
    (void)in_sizes; (void)n_in; (void)out_size;
    const float* x  = (const float*)d_in[0];
    const int*   L  = (const int*)  d_in[1];
    const float* W1 = (const float*)d_in[2];
    const float* b1 = (const float*)d_in[3];
    const float* W2 = (const float*)d_in[4];
    // d_in[5] = b2: constant shift on logits; cancels exactly in softmax.
    float* out = (float*)d_out;

    cudaFuncSetAttribute(k_gemm_mma, cudaFuncAttributeMaxDynamicSharedMemorySize, SMEM_GEMM);

    k_prepW<<<(Aa * K3C + 255) / 256, 256>>>(W1);
    k_scan_stats<<<Bb * Cc, 256>>>(x, L);
    dim3 g2(Tt / BM, Bb);
    k_gemm_mma<<<g2, 256, SMEM_GEMM>>>(b1, W2);
    k_softmax<<<Bb, 256>>>();
    k_weighted<<<Bb * Cc, 256>>>(x, out);
}

// round 9
// speedup vs baseline: 1.0137x; 1.0137x over previous
#include <cuda_runtime.h>
#include <cuda_bf16.h>
#include <cstdint>
#include <math.h>

// Problem constants
#define Bb   8
#define Cc   1536
#define Tt   4096
#define Aa   128
#define K3C  4608          // 3*C
#define EPSF 1e-12f

// ---------------- scratch (device globals; no allocation allowed) ----------------
__device__ __nv_bfloat16 g_xh[(size_t)Bb * Cc * Tt];   // x hi (96MB)
__device__ __nv_bfloat16 g_xl[(size_t)Bb * Cc * Tt];
__device__ __nv_bfloat16 g_mh[(size_t)Bb * Cc * Tt];   // mean hi
__device__ __nv_bfloat16 g_ml[(size_t)Bb * Cc * Tt];
__device__ __nv_bfloat16 g_sh[(size_t)Bb * Cc * Tt];   // std hi
__device__ __nv_bfloat16 g_sl[(size_t)Bb * Cc * Tt];
__device__ __nv_bfloat16 g_W1h[Aa * K3C];
__device__ __nv_bfloat16 g_W1l[Aa * K3C];
__device__ float g_logits[Bb * Tt];
__device__ float g_e     [Bb * Tt];
__device__ float g_Z     [Bb * Tt];

// ---------------- helpers ----------------
__device__ __forceinline__ uint32_t smem_u32(const void* p) {
    uint32_t a;
    asm("{ .reg .u64 t; cvta.to.shared.u64 t, %1; cvt.u32.u64 %0, t; }" : "=r"(a) : "l"(p));
    return a;
}
__device__ __forceinline__ int load_len(const int* __restrict__ L, int b) {
    return (L[1] == 0) ? L[2 * b] : L[b];   // int64 vs int32 detection
}
__device__ __forceinline__ void split_bf16(float v, __nv_bfloat16& h, __nv_bfloat16& l) {
    h = __float2bfloat16_rn(v);
    l = __float2bfloat16_rn(v - __bfloat162float(h));
}
__device__ __forceinline__ float fast_tanh(float v) {
    float e = __expf(2.f * v);          // inf-safe: e=inf -> 1, e=0 -> -1
    return 1.f - 2.f / (e + 1.f);
}
__device__ __forceinline__ float warp_iscan(float v, int lane) {
    #pragma unroll
    for (int off = 1; off < 32; off <<= 1) {
        float n = __shfl_up_sync(0xFFFFFFFFu, v, off);
        if (lane >= off) v += n;
    }
    return v;
}
// block-wide (256 thr) EXCLUSIVE scan of two values; 2 barriers.
__device__ __forceinline__ void block_exscan2(float& v1, float& v2, int tid,
                                              float* ws1, float* ws2) {
    int lane = tid & 31, wid = tid >> 5;
    float o1 = v1, o2 = v2;
    float i1 = warp_iscan(o1, lane), i2 = warp_iscan(o2, lane);
    if (lane == 31) { ws1[wid] = i1; ws2[wid] = i2; }
    __syncthreads();
    if (wid == 0) {
        float a1 = (lane < 8) ? ws1[lane] : 0.f;
        float a2 = (lane < 8) ? ws2[lane] : 0.f;
        float c1 = warp_iscan(a1, lane), c2 = warp_iscan(a2, lane);
        if (lane < 8) { ws1[lane] = c1; ws2[lane] = c2; }
    }
    __syncthreads();
    float p1 = wid ? ws1[wid - 1] : 0.f;
    float p2 = wid ? ws2[wid - 1] : 0.f;
    v1 = p1 + i1 - o1;
    v2 = p2 + i2 - o2;
}
__device__ __forceinline__ float block_exscan1(float v, int tid, float* ws) {
    int lane = tid & 31, wid = tid >> 5;
    float o = v;
    float i = warp_iscan(o, lane);
    if (lane == 31) ws[wid] = i;
    __syncthreads();
    if (wid == 0) {
        float a = (lane < 8) ? ws[lane] : 0.f;
        float c = warp_iscan(a, lane);
        if (lane < 8) ws[lane] = c;
    }
    __syncthreads();
    float p = wid ? ws[wid - 1] : 0.f;
    return p + i - o;
}

// ldmatrix / mma wrappers
__device__ __forceinline__ void ldsm_x4(uint32_t& r0, uint32_t& r1, uint32_t& r2, uint32_t& r3, uint32_t a) {
    asm volatile("ldmatrix.sync.aligned.m8n8.x4.shared.b16 {%0,%1,%2,%3}, [%4];"
                 : "=r"(r0), "=r"(r1), "=r"(r2), "=r"(r3) : "r"(a));
}
__device__ __forceinline__ void ldsm_x4_t(uint32_t& r0, uint32_t& r1, uint32_t& r2, uint32_t& r3, uint32_t a) {
    asm volatile("ldmatrix.sync.aligned.m8n8.x4.trans.shared.b16 {%0,%1,%2,%3}, [%4];"
                 : "=r"(r0), "=r"(r1), "=r"(r2), "=r"(r3) : "r"(a));
}
__device__ __forceinline__ void mma_bf16(float* d, const uint32_t* a, const uint32_t* b) {
    asm volatile(
        "mma.sync.aligned.m16n8k16.row.col.f32.bf16.bf16.f32 "
        "{%0,%1,%2,%3},{%4,%5,%6,%7},{%8,%9},{%0,%1,%2,%3};"
        : "+f"(d[0]), "+f"(d[1]), "+f"(d[2]), "+f"(d[3])
        : "r"(a[0]), "r"(a[1]), "r"(a[2]), "r"(a[3]), "r"(b[0]), "r"(b[1]));
}
__device__ __forceinline__ void cpa_cg(uint32_t dst, const void* src) {
    asm volatile("cp.async.cg.shared.global [%0], [%1], 16;" :: "r"(dst), "l"(src));
}
__device__ __forceinline__ void cpa_ca(uint32_t dst, const void* src) {
    asm volatile("cp.async.ca.shared.global [%0], [%1], 16;" :: "r"(dst), "l"(src));
}

// ---------------- K0: W1 -> bf16 hi/lo ----------------
__global__ __launch_bounds__(256) void k_prepW(const float* __restrict__ W1) {
    int i = blockIdx.x * 256 + threadIdx.x;
    if (i < Aa * K3C) {
        __nv_bfloat16 h, l;
        split_bf16(W1[i], h, l);
        g_W1h[i] = h; g_W1l[i] = l;
    }
}

// ---------------- K1: x -> bf16 hi/lo + causal mean/std -> bf16 hi/lo ----------------
__global__ __launch_bounds__(256) void k_scan_stats(const float* __restrict__ x,
                                                    const int* __restrict__ L) {
    int row = blockIdx.x;               // b*C + c
    int b = row / Cc;
    int len = load_len(L, b);

    __shared__ float xs[Tt];
    __shared__ float ss[Tt];
    __shared__ float ws1[8], ws2[8];

    int tid = threadIdx.x;
    const float* xr = x + (size_t)row * Tt;
    for (int j = tid; j < Tt; j += 256) xs[j] = xr[j];
    __syncthreads();

    size_t gb = (size_t)row * Tt;
    // write xh/xl, 8 bf16 packed per 16B store
    for (int g = tid; g < Tt / 8; g += 256) {
        int base = g * 8;
        uint4 ph, pl;
        unsigned short* hp = (unsigned short*)&ph;
        unsigned short* lp = (unsigned short*)&pl;
        #pragma unroll
        for (int k = 0; k < 8; k++) {
            __nv_bfloat16 h, l;
            split_bf16(xs[base + k], h, l);
            hp[k] = __bfloat16_as_ushort(h); lp[k] = __bfloat16_as_ushort(l);
        }
        *(uint4*)(g_xh + gb + base) = ph;
        *(uint4*)(g_xl + gb + base) = pl;
    }

    int base = tid * 16;
    float s1 = 0.f, s2 = 0.f;
    #pragma unroll
    for (int k = 0; k < 16; k++) {
        int t = base + k;
        float v = (t < len) ? xs[t] : 0.f;
        s1 += v; s2 += v * v;
    }
    // exclusive prefixes (internal barriers also fence the xh/xl reads above)
    block_exscan2(s1, s2, tid, ws1, ws2);

    float p1 = s1, p2 = s2;
    #pragma unroll
    for (int k = 0; k < 16; k++) {
        int t = base + k;
        float xv = xs[t];
        float v  = (t < len) ? xv : 0.f;
        p1 += v; p2 += v * v;
        int cn = min(t + 1, len); if (cn < 1) cn = 1;
        float cnf = (float)cn;
        float m   = p1 / cnf;
        float var = p2 / cnf - m * m;
        xs[t] = m;
        ss[t] = sqrtf(fmaxf(var, EPSF));
    }
    __syncthreads();

    for (int g = tid; g < Tt / 8; g += 256) {
        int bb = g * 8;
        uint4 mh, ml, sh, sl;
        unsigned short* mhp = (unsigned short*)&mh; unsigned short* mlp = (unsigned short*)&ml;
        unsigned short* shp = (unsigned short*)&sh; unsigned short* slp = (unsigned short*)&sl;
        #pragma unroll
        for (int k = 0; k < 8; k++) {
            __nv_bfloat16 h, l;
            split_bf16(xs[bb + k], h, l); mhp[k] = __bfloat16_as_ushort(h); mlp[k] = __bfloat16_as_ushort(l);
            split_bf16(ss[bb + k], h, l); shp[k] = __bfloat16_as_ushort(h); slp[k] = __bfloat16_as_ushort(l);
        }
        *(uint4*)(g_mh + gb + bb) = mh; *(uint4*)(g_ml + gb + bb) = ml;
        *(uint4*)(g_sh + gb + bb) = sh; *(uint4*)(g_sl + gb + bb) = sl;
    }
}

// ---------------- K2: 4-stage pipelined bf16 mma.sync GEMM + tanh + W2 reduce -> logits ----------------
#define BM 128
#define BK 32
#define NK (K3C / BK)        // 144
#define APITCH 272           // bytes per k-row (128 t * 2B + 16 pad)
#define BPITCH 80            // bytes per a-row (32 k * 2B + 16 pad)
#define OFF_AL 8704
#define OFF_BH 17408
#define OFF_BL 27648
#define SSTR   37888         // one stage: Ah+Al+Bh+Bl
#define NSTAGE 4
#define OFF_RED (NSTAGE * SSTR)
#define SMEM_GEMM (OFF_RED + 2 * BM * 4)    // 152576 B

__device__ __forceinline__ void gemm_load_tile(int j, uint32_t st, int b, int t0, int tid) {
    int k0 = j * BK;
    int region = k0 / Cc;                // 0:x 1:mean 2:std (BK=32 never straddles)
    int cb = k0 - region * Cc;
    const __nv_bfloat16* pH = (region == 0 ? g_xh : (region == 1 ? g_mh : g_sh))
                              + ((size_t)(b * Cc + cb)) * Tt + t0;
    const __nv_bfloat16* pL = (region == 0 ? g_xl : (region == 1 ? g_ml : g_sl))
                              + ((size_t)(b * Cc + cb)) * Tt + t0;
    #pragma unroll
    for (int p = 0; p < 2; p++) {
        int id = tid + p * 256;          // 0..511
        int r  = id >> 4, c = id & 15;   // A: 32 rows x 16 chunks(16B)
        cpa_cg(st + r * APITCH + c * 16,          pH + (size_t)r * Tt + c * 8);
        cpa_cg(st + OFF_AL + r * APITCH + c * 16, pL + (size_t)r * Tt + c * 8);
        int rb = id >> 2, cc = id & 3;   // B: 128 rows x 4 chunks(16B)
        cpa_ca(st + OFF_BH + rb * BPITCH + cc * 16, g_W1h + (size_t)rb * K3C + k0 + cc * 8);
        cpa_ca(st + OFF_BL + rb * BPITCH + cc * 16, g_W1l + (size_t)rb * K3C + k0 + cc * 8);
    }
}

__global__ __launch_bounds__(256) void k_gemm_mma(const float* __restrict__ b1,
                                                  const float* __restrict__ W2) {
    extern __shared__ __align__(16) char dsm[];
    uint32_t sb = smem_u32(dsm);

    int tid = threadIdx.x;
    int wid = tid >> 5, lid = tid & 31;
    int wm = wid & 3;          // 4 m-warps * 32 t
    int wn = wid >> 2;         // 2 n-warps * 64 a
    int b  = blockIdx.y, t0 = blockIdx.x * BM;

    // ldmatrix lane addressing
    int a_row_off = (lid & 7) + ((lid >> 4) << 3);
    int a_t_off   = wm * 32 + ((lid >> 3) & 1) * 8;
    int b_row     = wn * 64 + (lid & 7) + ((lid >> 4) << 3);
    int b_k_off   = ((lid >> 3) & 1) * 8;

    float acc[2][8][4];
    #pragma unroll
    for (int i = 0; i < 2; i++)
        #pragma unroll
        for (int j = 0; j < 8; j++)
            #pragma unroll
            for (int q = 0; q < 4; q++) acc[i][j][q] = 0.f;

    #pragma unroll
    for (int j = 0; j < NSTAGE - 1; j++) {
        gemm_load_tile(j, sb + j * SSTR, b, t0, tid);
        asm volatile("cp.async.commit_group;" ::: "memory");
    }

    for (int it = 0; it < NK; it++) {
        if (it + NSTAGE - 1 < NK)
            gemm_load_tile(it + NSTAGE - 1, sb + ((it + NSTAGE - 1) % NSTAGE) * SSTR, b, t0, tid);
        asm volatile("cp.async.commit_group;" ::: "memory");
        asm volatile("cp.async.wait_group 3;" ::: "memory");
        __syncthreads();

        uint32_t stb = sb + (it % NSTAGE) * SSTR;
        uint32_t uAh = stb, uAl = stb + OFF_AL, uBh = stb + OFF_BH, uBl = stb + OFF_BL;

        #pragma unroll
        for (int s = 0; s < 2; s++) {                 // two k16 steps
            uint32_t ah[2][4], al[2][4];
            #pragma unroll
            for (int mf = 0; mf < 2; mf++) {
                uint32_t addr = (s * 16 + a_row_off) * APITCH + (a_t_off + mf * 16) * 2;
                ldsm_x4_t(ah[mf][0], ah[mf][1], ah[mf][2], ah[mf][3], uAh + addr);
                ldsm_x4_t(al[mf][0], al[mf][1], al[mf][2], al[mf][3], uAl + addr);
            }
            #pragma unroll
            for (int nb2 = 0; nb2 < 4; nb2++) {       // 4 groups of 16 a
                uint32_t addr = (b_row + nb2 * 16) * BPITCH + (s * 16 + b_k_off) * 2;
                uint32_t bh[4], bl[4];
                ldsm_x4(bh[0], bh[1], bh[2], bh[3], uBh + addr);
                ldsm_x4(bl[0], bl[1], bl[2], bl[3], uBl + addr);
                #pragma unroll
                for (int half = 0; half < 2; half++) {
                    int nb = nb2 * 2 + half;
                    #pragma unroll
                    for (int mf = 0; mf < 2; mf++) {
                        mma_bf16(acc[mf][nb], ah[mf], bh + half * 2);
                        mma_bf16(acc[mf][nb], al[mf], bh + half * 2);
                        mma_bf16(acc[mf][nb], ah[mf], bl + half * 2);
                    }
                }
            }
        }
        __syncthreads();
    }

    // ---- epilogue: h = tanh(acc + b1[a]); row-sum of W2[a]*h over a ----
    float* red = (float*)(dsm + OFF_RED);   // [2][BM]
    float rs[2][2] = {{0.f, 0.f}, {0.f, 0.f}};
    #pragma unroll
    for (int nb = 0; nb < 8; nb++) {
        int a0 = wn * 64 + nb * 8 + (lid & 3) * 2;
        float w20 = __ldg(&W2[a0]),   w21 = __ldg(&W2[a0 + 1]);
        float b10 = __ldg(&b1[a0]),   b11 = __ldg(&b1[a0 + 1]);
        #pragma unroll
        for (int mf = 0; mf < 2; mf++) {
            rs[mf][0] += w20 * fast_tanh(acc[mf][nb][0] + b10)
                       + w21 * fast_tanh(acc[mf][nb][1] + b11);
            rs[mf][1] += w20 * fast_tanh(acc[mf][nb][2] + b10)
                       + w21 * fast_tanh(acc[mf][nb][3] + b11);
        }
    }
    #pragma unroll
    for (int mf = 0; mf < 2; mf++)
        #pragma unroll
        for (int r = 0; r < 2; r++) {
            rs[mf][r] += __shfl_xor_sync(0xFFFFFFFF, rs[mf][r], 1);
            rs[mf][r] += __shfl_xor_sync(0xFFFFFFFF, rs[mf][r], 2);
        }
    if ((lid & 3) == 0) {
        int trow = wm * 32 + (lid >> 2);
        #pragma unroll
        for (int mf = 0; mf < 2; mf++) {
            red[wn * BM + trow + mf * 16]     = rs[mf][0];
            red[wn * BM + trow + mf * 16 + 8] = rs[mf][1];
        }
    }
    __syncthreads();
    if (tid < BM)
        g_logits[b * Tt + t0 + tid] = red[tid] + red[BM + tid];
}

// ---------------- K3: per-batch max, exp, cumsum -> e, Z ----------------
__global__ __launch_bounds__(256) void k_softmax() {
    int b = blockIdx.x;
    __shared__ float sm[Tt];
    __shared__ float red[256];
    __shared__ float ws[8];
    int tid = threadIdx.x;

    const float* lr = g_logits + b * Tt;
    float mx = -INFINITY;
    for (int j = tid; j < Tt; j += 256) { float v = lr[j]; sm[j] = v; mx = fmaxf(mx, v); }
    red[tid] = mx;
    __syncthreads();
    for (int off = 128; off; off >>= 1) {
        if (tid < off) red[tid] = fmaxf(red[tid], red[tid + off]);
        __syncthreads();
    }
    float M = red[0];
    __syncthreads();

    int base = tid * 16;
    float s = 0.f;
    #pragma unroll
    for (int k = 0; k < 16; k++) {
        float ev = expf(sm[base + k] - M);
        sm[base + k] = ev;
        s += ev;
    }
    float p = block_exscan1(s, tid, ws);
    #pragma unroll
    for (int k = 0; k < 16; k++) {
        int t = base + k;
        float ev = sm[t];
        p += ev;
        g_e[b * Tt + t] = ev;
        g_Z[b * Tt + t] = p;
    }
}

// ---------------- K4: weighted mean/std scans + final reduction ----------------
__global__ __launch_bounds__(256) void k_weighted(const float* __restrict__ x,
                                                  float* __restrict__ out) {
    int row = blockIdx.x;
    int b = row / Cc;
    int c = row - b * Cc;

    __shared__ float xs[Tt];
    __shared__ float es[Tt];
    __shared__ float ws[8];
    __shared__ float w1s[256], w2s[256];

    int tid = threadIdx.x;
    const float* xr = x + (size_t)row * Tt;
    const float* er = g_e + b * Tt;
    const float* zr = g_Z + b * Tt;
    for (int j = tid; j < Tt; j += 256) { xs[j] = xr[j]; es[j] = er[j]; }
    __syncthreads();

    int base = tid * 16;

    float s = 0.f;
    #pragma unroll
    for (int k = 0; k < 16; k++) { int t = base + k; s += es[t] * xs[t]; }
    float p = block_exscan1(s, tid, ws);

    float sum_wm = 0.f, s2 = 0.f;
    #pragma unroll
    for (int k = 0; k < 16; k++) {
        int t = base + k;
        p += es[t] * xs[t];
        float wm = p / zr[t];
        sum_wm += wm;
        float d = xs[t] - wm;
        float v = es[t] * d * d;
        xs[t] = v;
        s2 += v;
    }
    __syncthreads();   // ws reuse fence

    float q = block_exscan1(s2, tid, ws);
    float sum_ws = 0.f;
    #pragma unroll
    for (int k = 0; k < 16; k++) {
        int t = base + k;
        q += xs[t];
        float wv = q / zr[t];
        sum_ws += sqrtf(fmaxf(wv, EPSF));
    }
    __syncthreads();

    w1s[tid] = sum_wm;
    w2s[tid] = sum_ws;
    __syncthreads();
    for (int off = 128; off; off >>= 1) {
        if (tid < off) { w1s[tid] += w1s[tid + off]; w2s[tid] += w2s[tid + off]; }
        __syncthreads();
    }
    if (tid == 0) {
        const float FW = (float)(1.0 / (4096.0 + 1e-12));
        out[(size_t)b * 2 * Cc + c]      = w1s[0] * FW;
        out[(size_t)b * 2 * Cc + Cc + c] = w2s[0] * FW;
    }
}

// ---------------- launch ----------------
extern "C" void kernel_launch(void* const* d_in, const int* in_sizes, int n_in,
                              void* d_out, int out_size) {
    (void)in_sizes; (void)n_in; (void)out_size;
    const float* x  = (const float*)d_in[0];
    const int*   L  = (const int*)  d_in[1];
    const float* W1 = (const float*)d_in[2];
    const float* b1 = (const float*)d_in[3];
    const float* W2 = (const float*)d_in[4];
    // d_in[5] = b2: constant shift on logits; cancels exactly in softmax.
    float* out = (float*)d_out;

    cudaFuncSetAttribute(k_gemm_mma, cudaFuncAttributeMaxDynamicSharedMemorySize, SMEM_GEMM);

    k_prepW<<<(Aa * K3C + 255) / 256, 256>>>(W1);
    k_scan_stats<<<Bb * Cc, 256>>>(x, L);
    dim3 g2(Tt / BM, Bb);
    k_gemm_mma<<<g2, 256, SMEM_GEMM>>>(b1, W2);
    k_softmax<<<Bb, 256>>>();
    k_weighted<<<Bb * Cc, 256>>>(x, out);
}

// round 11
// speedup vs baseline: 1.6355x; 1.6134x over previous
#include <cuda_runtime.h>
#include <cuda_bf16.h>
#include <cstdint>
#include <math.h>

// Problem constants
#define Bb   8
#define Cc   1536
#define Tt   4096
#define Aa   128
#define K3C  4608          // 3*C
#define EPSF 1e-12f

// ---------------- scratch (device globals; no allocation allowed) ----------------
__device__ __nv_bfloat16 g_xh[(size_t)Bb * Cc * Tt];   // x hi (96MB)
__device__ __nv_bfloat16 g_xl[(size_t)Bb * Cc * Tt];
__device__ __nv_bfloat16 g_mh[(size_t)Bb * Cc * Tt];   // mean hi
__device__ __nv_bfloat16 g_ml[(size_t)Bb * Cc * Tt];
__device__ __nv_bfloat16 g_sh[(size_t)Bb * Cc * Tt];   // std hi
__device__ __nv_bfloat16 g_sl[(size_t)Bb * Cc * Tt];
__device__ __nv_bfloat16 g_W1h[Aa * K3C];
__device__ __nv_bfloat16 g_W1l[Aa * K3C];
__device__ float g_logits[Bb * Tt];
__device__ float g_e     [Bb * Tt];
__device__ float g_Z     [Bb * Tt];

// ---------------- helpers ----------------
__device__ __forceinline__ uint32_t smem_u32(const void* p) {
    uint32_t a;
    asm("{ .reg .u64 t; cvta.to.shared.u64 t, %1; cvt.u32.u64 %0, t; }" : "=r"(a) : "l"(p));
    return a;
}
__device__ __forceinline__ int load_len(const int* __restrict__ L, int b) {
    return (L[1] == 0) ? L[2 * b] : L[b];   // int64 vs int32 detection
}
__device__ __forceinline__ void split_bf16(float v, __nv_bfloat16& h, __nv_bfloat16& l) {
    h = __float2bfloat16_rn(v);
    l = __float2bfloat16_rn(v - __bfloat162float(h));
}
__device__ __forceinline__ float fast_tanh(float v) {
    float e = __expf(2.f * v);          // inf-safe: e=inf -> 1, e=0 -> -1
    return 1.f - 2.f / (e + 1.f);
}
__device__ __forceinline__ float warp_iscan(float v, int lane) {
    #pragma unroll
    for (int off = 1; off < 32; off <<= 1) {
        float n = __shfl_up_sync(0xFFFFFFFFu, v, off);
        if (lane >= off) v += n;
    }
    return v;
}
// block-wide (256 thr) EXCLUSIVE scan of two values; 2 barriers.
__device__ __forceinline__ void block_exscan2(float& v1, float& v2, int tid,
                                              float* ws1, float* ws2) {
    int lane = tid & 31, wid = tid >> 5;
    float o1 = v1, o2 = v2;
    float i1 = warp_iscan(o1, lane), i2 = warp_iscan(o2, lane);
    if (lane == 31) { ws1[wid] = i1; ws2[wid] = i2; }
    __syncthreads();
    if (wid == 0) {
        float a1 = (lane < 8) ? ws1[lane] : 0.f;
        float a2 = (lane < 8) ? ws2[lane] : 0.f;
        float c1 = warp_iscan(a1, lane), c2 = warp_iscan(a2, lane);
        if (lane < 8) { ws1[lane] = c1; ws2[lane] = c2; }
    }
    __syncthreads();
    float p1 = wid ? ws1[wid - 1] : 0.f;
    float p2 = wid ? ws2[wid - 1] : 0.f;
    v1 = p1 + i1 - o1;
    v2 = p2 + i2 - o2;
}
__device__ __forceinline__ float block_exscan1(float v, int tid, float* ws) {
    int lane = tid & 31, wid = tid >> 5;
    float o = v;
    float i = warp_iscan(o, lane);
    if (lane == 31) ws[wid] = i;
    __syncthreads();
    if (wid == 0) {
        float a = (lane < 8) ? ws[lane] : 0.f;
        float c = warp_iscan(a, lane);
        if (lane < 8) ws[lane] = c;
    }
    __syncthreads();
    float p = wid ? ws[wid - 1] : 0.f;
    return p + i - o;
}

// ldmatrix / mma wrappers
__device__ __forceinline__ void ldsm_x4(uint32_t& r0, uint32_t& r1, uint32_t& r2, uint32_t& r3, uint32_t a) {
    asm volatile("ldmatrix.sync.aligned.m8n8.x4.shared.b16 {%0,%1,%2,%3}, [%4];"
                 : "=r"(r0), "=r"(r1), "=r"(r2), "=r"(r3) : "r"(a));
}
__device__ __forceinline__ void ldsm_x4_t(uint32_t& r0, uint32_t& r1, uint32_t& r2, uint32_t& r3, uint32_t a) {
    asm volatile("ldmatrix.sync.aligned.m8n8.x4.trans.shared.b16 {%0,%1,%2,%3}, [%4];"
                 : "=r"(r0), "=r"(r1), "=r"(r2), "=r"(r3) : "r"(a));
}
__device__ __forceinline__ void mma_bf16(float* d, const uint32_t* a, const uint32_t* b) {
    asm volatile(
        "mma.sync.aligned.m16n8k16.row.col.f32.bf16.bf16.f32 "
        "{%0,%1,%2,%3},{%4,%5,%6,%7},{%8,%9},{%0,%1,%2,%3};"
        : "+f"(d[0]), "+f"(d[1]), "+f"(d[2]), "+f"(d[3])
        : "r"(a[0]), "r"(a[1]), "r"(a[2]), "r"(a[3]), "r"(b[0]), "r"(b[1]));
}

// ---------------- K0: W1 -> bf16 hi/lo ----------------
__global__ __launch_bounds__(256) void k_prepW(const float* __restrict__ W1) {
    int i = blockIdx.x * 256 + threadIdx.x;
    if (i < Aa * K3C) {
        __nv_bfloat16 h, l;
        split_bf16(W1[i], h, l);
        g_W1h[i] = h; g_W1l[i] = l;
    }
}

// ---------------- K1: x -> bf16 hi/lo + causal mean/std -> bf16 hi/lo ----------------
__global__ __launch_bounds__(256) void k_scan_stats(const float* __restrict__ x,
                                                    const int* __restrict__ L) {
    int row = blockIdx.x;               // b*C + c
    int b = row / Cc;
    int len = load_len(L, b);

    __shared__ float xs[Tt];
    __shared__ float ss[Tt];
    __shared__ float ws1[8], ws2[8];

    int tid = threadIdx.x;
    const float* xr = x + (size_t)row * Tt;
    for (int j = tid; j < Tt; j += 256) xs[j] = xr[j];
    __syncthreads();

    size_t gb = (size_t)row * Tt;
    // write xh/xl, 8 bf16 packed per 16B store
    for (int g = tid; g < Tt / 8; g += 256) {
        int base = g * 8;
        uint4 ph, pl;
        unsigned short* hp = (unsigned short*)&ph;
        unsigned short* lp = (unsigned short*)&pl;
        #pragma unroll
        for (int k = 0; k < 8; k++) {
            __nv_bfloat16 h, l;
            split_bf16(xs[base + k], h, l);
            hp[k] = __bfloat16_as_ushort(h); lp[k] = __bfloat16_as_ushort(l);
        }
        *(uint4*)(g_xh + gb + base) = ph;
        *(uint4*)(g_xl + gb + base) = pl;
    }

    int base = tid * 16;
    float s1 = 0.f, s2 = 0.f;
    #pragma unroll
    for (int k = 0; k < 16; k++) {
        int t = base + k;
        float v = (t < len) ? xs[t] : 0.f;
        s1 += v; s2 += v * v;
    }
    // exclusive prefixes (internal barriers also fence the xh/xl reads above)
    block_exscan2(s1, s2, tid, ws1, ws2);

    float p1 = s1, p2 = s2;
    #pragma unroll
    for (int k = 0; k < 16; k++) {
        int t = base + k;
        float xv = xs[t];
        float v  = (t < len) ? xv : 0.f;
        p1 += v; p2 += v * v;
        int cn = min(t + 1, len); if (cn < 1) cn = 1;
        float cnf = (float)cn;
        float m   = p1 / cnf;
        float var = p2 / cnf - m * m;
        xs[t] = m;
        ss[t] = sqrtf(fmaxf(var, EPSF));
    }
    __syncthreads();

    for (int g = tid; g < Tt / 8; g += 256) {
        int bb = g * 8;
        uint4 mh, ml, sh, sl;
        unsigned short* mhp = (unsigned short*)&mh; unsigned short* mlp = (unsigned short*)&ml;
        unsigned short* shp = (unsigned short*)&sh; unsigned short* slp = (unsigned short*)&sl;
        #pragma unroll
        for (int k = 0; k < 8; k++) {
            __nv_bfloat16 h, l;
            split_bf16(xs[bb + k], h, l); mhp[k] = __bfloat16_as_ushort(h); mlp[k] = __bfloat16_as_ushort(l);
            split_bf16(ss[bb + k], h, l); shp[k] = __bfloat16_as_ushort(h); slp[k] = __bfloat16_as_ushort(l);
        }
        *(uint4*)(g_mh + gb + bb) = mh; *(uint4*)(g_ml + gb + bb) = ml;
        *(uint4*)(g_sh + gb + bb) = sh; *(uint4*)(g_sl + gb + bb) = sl;
    }
}

// ---------------- marker: aligns ncu's captured slot onto the GEMM ----------------
__global__ void k_marker() {}

// ---------------- K2: double-buffered bf16 mma.sync GEMM (512 thr) + tanh + W2 reduce ----------------
#define BM 128
#define BK 32
#define NK (K3C / BK)        // 144
#define APITCH 272           // bytes per k-row (128 t * 2B + 16 pad)
#define BPITCH 80            // bytes per a-row (32 k * 2B + 16 pad)
#define OFF_AL 8704
#define OFF_BH 17408
#define OFF_BL 27648
#define SSTR   37888         // one stage: Ah+Al+Bh+Bl
#define OFF_RED (2 * SSTR)   // 75776
#define SMEM_GEMM (OFF_RED + 4 * BM * 4)    // 77824 B

struct StageRegs { uint4 ah, al, bh, bl; };

__device__ __forceinline__ StageRegs gemm_ldg(int j, int b, int t0, int tid) {
    int k0 = j * BK;
    int region = k0 / Cc;                // 0:x 1:mean 2:std (BK=32 never straddles)
    int cb = k0 - region * Cc;
    const __nv_bfloat16* pH = (region == 0 ? g_xh : (region == 1 ? g_mh : g_sh))
                              + ((size_t)(b * Cc + cb)) * Tt + t0;
    const __nv_bfloat16* pL = (region == 0 ? g_xl : (region == 1 ? g_ml : g_sl))
                              + ((size_t)(b * Cc + cb)) * Tt + t0;
    StageRegs s;
    int r  = tid >> 4, c  = tid & 15;    // A: 32 k-rows x 16 chunks(16B)
    s.ah = *(const uint4*)(pH + (size_t)r * Tt + c * 8);
    s.al = *(const uint4*)(pL + (size_t)r * Tt + c * 8);
    int rb = tid >> 2, cc = tid & 3;     // B: 128 a-rows x 4 chunks(16B)
    s.bh = *(const uint4*)(g_W1h + (size_t)rb * K3C + k0 + cc * 8);
    s.bl = *(const uint4*)(g_W1l + (size_t)rb * K3C + k0 + cc * 8);
    return s;
}

__device__ __forceinline__ void gemm_sts(char* st, const StageRegs& s, int tid) {
    int r  = tid >> 4, c  = tid & 15;
    *(uint4*)(st + r * APITCH + c * 16)           = s.ah;
    *(uint4*)(st + OFF_AL + r * APITCH + c * 16)  = s.al;
    int rb = tid >> 2, cc = tid & 3;
    *(uint4*)(st + OFF_BH + rb * BPITCH + cc * 16) = s.bh;
    *(uint4*)(st + OFF_BL + rb * BPITCH + cc * 16) = s.bl;
}

__global__ __launch_bounds__(512) void k_gemm_mma(const float* __restrict__ b1,
                                                  const float* __restrict__ W2) {
    extern __shared__ __align__(16) char dsm[];
    uint32_t sb = smem_u32(dsm);

    int tid = threadIdx.x;
    int wid = tid >> 5, lid = tid & 31;
    int wm = wid & 3;          // 4 m-groups * 32 t
    int wn = wid >> 2;         // 4 n-groups * 32 a
    int b  = blockIdx.y, t0 = blockIdx.x * BM;

    // ldmatrix lane addressing
    int a_row_off = (lid & 7) + ((lid >> 4) << 3);
    int a_t_off   = wm * 32 + ((lid >> 3) & 1) * 8;
    int b_row     = wn * 32 + (lid & 7) + ((lid >> 4) << 3);
    int b_k_off   = ((lid >> 3) & 1) * 8;

    float acc[2][4][4];      // [mf t-frag][nb 8a group][frag]
    #pragma unroll
    for (int i = 0; i < 2; i++)
        #pragma unroll
        for (int j = 0; j < 4; j++)
            #pragma unroll
            for (int q = 0; q < 4; q++) acc[i][j][q] = 0.f;

    // prologue: tile 0 -> regs -> smem buf0
    StageRegs sr = gemm_ldg(0, b, t0, tid);
    gemm_sts(dsm, sr, tid);
    __syncthreads();

    for (int it = 0; it < NK; it++) {
        bool has_next = (it + 1) < NK;
        if (has_next) sr = gemm_ldg(it + 1, b, t0, tid);

        uint32_t stb = sb + (it & 1) * SSTR;
        uint32_t uAh = stb, uAl = stb + OFF_AL, uBh = stb + OFF_BH, uBl = stb + OFF_BL;

        #pragma unroll
        for (int s = 0; s < 2; s++) {                 // two k16 steps
            uint32_t ah[2][4], al[2][4];
            #pragma unroll
            for (int mf = 0; mf < 2; mf++) {
                uint32_t addr = (s * 16 + a_row_off) * APITCH + (a_t_off + mf * 16) * 2;
                ldsm_x4_t(ah[mf][0], ah[mf][1], ah[mf][2], ah[mf][3], uAh + addr);
                ldsm_x4_t(al[mf][0], al[mf][1], al[mf][2], al[mf][3], uAl + addr);
            }
            #pragma unroll
            for (int nb2 = 0; nb2 < 2; nb2++) {       // 2 groups of 16 a
                uint32_t addr = (b_row + nb2 * 16) * BPITCH + (s * 16 + b_k_off) * 2;
                uint32_t bh[4], bl[4];
                ldsm_x4(bh[0], bh[1], bh[2], bh[3], uBh + addr);
                ldsm_x4(bl[0], bl[1], bl[2], bl[3], uBl + addr);
                #pragma unroll
                for (int half = 0; half < 2; half++) {
                    int nb = nb2 * 2 + half;
                    #pragma unroll
                    for (int mf = 0; mf < 2; mf++) {
                        mma_bf16(acc[mf][nb], ah[mf], bh + half * 2);
                        mma_bf16(acc[mf][nb], al[mf], bh + half * 2);
                        mma_bf16(acc[mf][nb], ah[mf], bl + half * 2);
                    }
                }
            }
        }
        // write next tile into the other buffer (not read by this iteration)
        if (has_next) gemm_sts(dsm + ((it + 1) & 1) * SSTR, sr, tid);
        __syncthreads();
    }

    // ---- epilogue: h = tanh(acc + b1[a]); row-sum of W2[a]*h over a ----
    float* red = (float*)(dsm + OFF_RED);   // [4][BM]
    float rs[2][2] = {{0.f, 0.f}, {0.f, 0.f}};
    #pragma unroll
    for (int nb = 0; nb < 4; nb++) {
        int a0 = wn * 32 + nb * 8 + (lid & 3) * 2;
        float w20 = __ldg(&W2[a0]),   w21 = __ldg(&W2[a0 + 1]);
        float b10 = __ldg(&b1[a0]),   b11 = __ldg(&b1[a0 + 1]);
        #pragma unroll
        for (int mf = 0; mf < 2; mf++) {
            rs[mf][0] += w20 * fast_tanh(acc[mf][nb][0] + b10)
                       + w21 * fast_tanh(acc[mf][nb][1] + b11);
            rs[mf][1] += w20 * fast_tanh(acc[mf][nb][2] + b10)
                       + w21 * fast_tanh(acc[mf][nb][3] + b11);
        }
    }
    #pragma unroll
    for (int mf = 0; mf < 2; mf++)
        #pragma unroll
        for (int r = 0; r < 2; r++) {
            rs[mf][r] += __shfl_xor_sync(0xFFFFFFFF, rs[mf][r], 1);
            rs[mf][r] += __shfl_xor_sync(0xFFFFFFFF, rs[mf][r], 2);
        }
    if ((lid & 3) == 0) {
        int trow = wm * 32 + (lid >> 2);
        #pragma unroll
        for (int mf = 0; mf < 2; mf++) {
            red[wn * BM + trow + mf * 16]     = rs[mf][0];
            red[wn * BM + trow + mf * 16 + 8] = rs[mf][1];
        }
    }
    __syncthreads();
    if (tid < BM)
        g_logits[b * Tt + t0 + tid] = red[tid] + red[BM + tid] + red[2 * BM + tid] + red[3 * BM + tid];
}

// ---------------- K3: per-batch max, exp, cumsum -> e, Z ----------------
__global__ __launch_bounds__(256) void k_softmax() {
    int b = blockIdx.x;
    __shared__ float sm[Tt];
    __shared__ float red[256];
    __shared__ float ws[8];
    int tid = threadIdx.x;

    const float* lr = g_logits + b * Tt;
    float mx = -INFINITY;
    for (int j = tid; j < Tt; j += 256) { float v = lr[j]; sm[j] = v; mx = fmaxf(mx, v); }
    red[tid] = mx;
    __syncthreads();
    for (int off = 128; off; off >>= 1) {
        if (tid < off) red[tid] = fmaxf(red[tid], red[tid + off]);
        __syncthreads();
    }
    float M = red[0];
    __syncthreads();

    int base = tid * 16;
    float s = 0.f;
    #pragma unroll
    for (int k = 0; k < 16; k++) {
        float ev = expf(sm[base + k] - M);
        sm[base + k] = ev;
        s += ev;
    }
    float p = block_exscan1(s, tid, ws);
    #pragma unroll
    for (int k = 0; k < 16; k++) {
        int t = base + k;
        float ev = sm[t];
        p += ev;
        g_e[b * Tt + t] = ev;
        g_Z[b * Tt + t] = p;
    }
}

// ---------------- K4: weighted mean/std scans + final reduction ----------------
__global__ __launch_bounds__(256) void k_weighted(const float* __restrict__ x,
                                                  float* __restrict__ out) {
    int row = blockIdx.x;
    int b = row / Cc;
    int c = row - b * Cc;

    __shared__ float xs[Tt];
    __shared__ float es[Tt];
    __shared__ float ws[8];
    __shared__ float w1s[256], w2s[256];

    int tid = threadIdx.x;
    const float* xr = x + (size_t)row * Tt;
    const float* er = g_e + b * Tt;
    const float* zr = g_Z + b * Tt;
    for (int j = tid; j < Tt; j += 256) { xs[j] = xr[j]; es[j] = er[j]; }
    __syncthreads();

    int base = tid * 16;

    float s = 0.f;
    #pragma unroll
    for (int k = 0; k < 16; k++) { int t = base + k; s += es[t] * xs[t]; }
    float p = block_exscan1(s, tid, ws);

    float sum_wm = 0.f, s2 = 0.f;
    #pragma unroll
    for (int k = 0; k < 16; k++) {
        int t = base + k;
        p += es[t] * xs[t];
        float wm = p / zr[t];
        sum_wm += wm;
        float d = xs[t] - wm;
        float v = es[t] * d * d;
        xs[t] = v;
        s2 += v;
    }
    __syncthreads();   // ws reuse fence

    float q = block_exscan1(s2, tid, ws);
    float sum_ws = 0.f;
    #pragma unroll
    for (int k = 0; k < 16; k++) {
        int t = base + k;
        q += xs[t];
        float wv = q / zr[t];
        sum_ws += sqrtf(fmaxf(wv, EPSF));
    }
    __syncthreads();

    w1s[tid] = sum_wm;
    w2s[tid] = sum_ws;
    __syncthreads();
    for (int off = 128; off; off >>= 1) {
        if (tid < off) { w1s[tid] += w1s[tid + off]; w2s[tid] += w2s[tid + off]; }
        __syncthreads();
    }
    if (tid == 0) {
        const float FW = (float)(1.0 / (4096.0 + 1e-12));
        out[(size_t)b * 2 * Cc + c]      = w1s[0] * FW;
        out[(size_t)b * 2 * Cc + Cc + c] = w2s[0] * FW;
    }
}

// ---------------- launch ----------------
extern "C" void kernel_launch(void* const* d_in, const int* in_sizes, int n_in,
                              void* d_out, int out_size) {
    (void)in_sizes; (void)n_in; (void)out_size;
    const float* x  = (const float*)d_in[0];
    const int*   L  = (const int*)  d_in[1];
    const float* W1 = (const float*)d_in[2];
    const float* b1 = (const float*)d_in[3];
    const float* W2 = (const float*)d_in[4];
    // d_in[5] = b2: constant shift on logits; cancels exactly in softmax.
    float* out = (float*)d_out;

    cudaFuncSetAttribute(k_gemm_mma, cudaFuncAttributeMaxDynamicSharedMemorySize, SMEM_GEMM);

    k_prepW<<<(Aa * K3C + 255) / 256, 256>>>(W1);
    k_scan_stats<<<Bb * Cc, 256>>>(x, L);
    k_marker<<<1, 32>>>();                     // shifts ncu's captured slot onto k_gemm_mma
    dim3 g2(Tt / BM, Bb);
    k_gemm_mma<<<g2, 512, SMEM_GEMM>>>(b1, W2);
    k_softmax<<<Bb, 256>>>();
    k_weighted<<<Bb * Cc, 256>>>(x, out);
}

// round 12
// speedup vs baseline: 1.7472x; 1.0683x over previous
#include <cuda_runtime.h>
#include <cuda_bf16.h>
#include <cstdint>
#include <math.h>

// Problem constants
#define Bb   8
#define Cc   1536
#define Tt   4096
#define Aa   128
#define K3C  4608          // 3*C
#define EPSF 1e-12f

// ---------------- scratch (device globals; no allocation allowed) ----------------
__device__ __nv_bfloat16 g_xh[(size_t)Bb * Cc * Tt];   // x hi (96MB)
__device__ __nv_bfloat16 g_xl[(size_t)Bb * Cc * Tt];
__device__ __nv_bfloat16 g_mh[(size_t)Bb * Cc * Tt];   // mean hi
__device__ __nv_bfloat16 g_ml[(size_t)Bb * Cc * Tt];
__device__ __nv_bfloat16 g_sh[(size_t)Bb * Cc * Tt];   // std hi
__device__ __nv_bfloat16 g_sl[(size_t)Bb * Cc * Tt];
__device__ __nv_bfloat16 g_W1h[Aa * K3C];
__device__ __nv_bfloat16 g_W1l[Aa * K3C];
__device__ float g_logits[Bb * Tt];
__device__ float g_e     [Bb * Tt];
__device__ float g_Z     [Bb * Tt];
__device__ float g_Zi    [Bb * Tt];   // 1/Z, precomputed in K3

// ---------------- helpers ----------------
__device__ __forceinline__ uint32_t smem_u32(const void* p) {
    uint32_t a;
    asm("{ .reg .u64 t; cvta.to.shared.u64 t, %1; cvt.u32.u64 %0, t; }" : "=r"(a) : "l"(p));
    return a;
}
__device__ __forceinline__ int load_len(const int* __restrict__ L, int b) {
    return (L[1] == 0) ? L[2 * b] : L[b];   // int64 vs int32 detection
}
__device__ __forceinline__ void split_bf16(float v, __nv_bfloat16& h, __nv_bfloat16& l) {
    h = __float2bfloat16_rn(v);
    l = __float2bfloat16_rn(v - __bfloat162float(h));
}
__device__ __forceinline__ float fast_tanh(float v) {
    float e = __expf(2.f * v);          // inf-safe: e=inf -> 1, e=0 -> -1
    return 1.f - 2.f / (e + 1.f);
}
// fast sqrt for v >= EPSF: v * rsqrt(v)
__device__ __forceinline__ float fast_sqrt(float v) {
    return v * __frsqrt_rn(v);
}
__device__ __forceinline__ float warp_iscan(float v, int lane) {
    #pragma unroll
    for (int off = 1; off < 32; off <<= 1) {
        float n = __shfl_up_sync(0xFFFFFFFFu, v, off);
        if (lane >= off) v += n;
    }
    return v;
}
// block-wide (256 thr) EXCLUSIVE scan of two values; 2 barriers.
__device__ __forceinline__ void block_exscan2(float& v1, float& v2, int tid,
                                              float* ws1, float* ws2) {
    int lane = tid & 31, wid = tid >> 5;
    float o1 = v1, o2 = v2;
    float i1 = warp_iscan(o1, lane), i2 = warp_iscan(o2, lane);
    if (lane == 31) { ws1[wid] = i1; ws2[wid] = i2; }
    __syncthreads();
    if (wid == 0) {
        float a1 = (lane < 8) ? ws1[lane] : 0.f;
        float a2 = (lane < 8) ? ws2[lane] : 0.f;
        float c1 = warp_iscan(a1, lane), c2 = warp_iscan(a2, lane);
        if (lane < 8) { ws1[lane] = c1; ws2[lane] = c2; }
    }
    __syncthreads();
    float p1 = wid ? ws1[wid - 1] : 0.f;
    float p2 = wid ? ws2[wid - 1] : 0.f;
    v1 = p1 + i1 - o1;
    v2 = p2 + i2 - o2;
}
__device__ __forceinline__ float block_exscan1(float v, int tid, float* ws) {
    int lane = tid & 31, wid = tid >> 5;
    float o = v;
    float i = warp_iscan(o, lane);
    if (lane == 31) ws[wid] = i;
    __syncthreads();
    if (wid == 0) {
        float a = (lane < 8) ? ws[lane] : 0.f;
        float c = warp_iscan(a, lane);
        if (lane < 8) ws[lane] = c;
    }
    __syncthreads();
    float p = wid ? ws[wid - 1] : 0.f;
    return p + i - o;
}

// ldmatrix / mma wrappers
__device__ __forceinline__ void ldsm_x4(uint32_t& r0, uint32_t& r1, uint32_t& r2, uint32_t& r3, uint32_t a) {
    asm volatile("ldmatrix.sync.aligned.m8n8.x4.shared.b16 {%0,%1,%2,%3}, [%4];"
                 : "=r"(r0), "=r"(r1), "=r"(r2), "=r"(r3) : "r"(a));
}
__device__ __forceinline__ void ldsm_x4_t(uint32_t& r0, uint32_t& r1, uint32_t& r2, uint32_t& r3, uint32_t a) {
    asm volatile("ldmatrix.sync.aligned.m8n8.x4.trans.shared.b16 {%0,%1,%2,%3}, [%4];"
                 : "=r"(r0), "=r"(r1), "=r"(r2), "=r"(r3) : "r"(a));
}
__device__ __forceinline__ void mma_bf16(float* d, const uint32_t* a, const uint32_t* b) {
    asm volatile(
        "mma.sync.aligned.m16n8k16.row.col.f32.bf16.bf16.f32 "
        "{%0,%1,%2,%3},{%4,%5,%6,%7},{%8,%9},{%0,%1,%2,%3};"
        : "+f"(d[0]), "+f"(d[1]), "+f"(d[2]), "+f"(d[3])
        : "r"(a[0]), "r"(a[1]), "r"(a[2]), "r"(a[3]), "r"(b[0]), "r"(b[1]));
}

// ---------------- K0: W1 -> bf16 hi/lo ----------------
__global__ __launch_bounds__(256) void k_prepW(const float* __restrict__ W1) {
    int i = blockIdx.x * 256 + threadIdx.x;
    if (i < Aa * K3C) {
        __nv_bfloat16 h, l;
        split_bf16(W1[i], h, l);
        g_W1h[i] = h; g_W1l[i] = l;
    }
}

// ---------------- marker: aligns ncu's captured 4th slot onto k_scan_stats ----------------
__global__ void k_marker() {}
__global__ void k_marker2() {}

// ---------------- K1: x -> bf16 hi/lo + causal mean/std -> bf16 hi/lo ----------------
__global__ __launch_bounds__(256) void k_scan_stats(const float* __restrict__ x,
                                                    const int* __restrict__ L) {
    int row = blockIdx.x;               // b*C + c
    int b = row / Cc;
    int len = load_len(L, b);

    __shared__ float xs[Tt];
    __shared__ float ss[Tt];
    __shared__ float ws1[8], ws2[8];

    int tid = threadIdx.x;
    const float* xr = x + (size_t)row * Tt;
    for (int j = tid; j < Tt; j += 256) xs[j] = xr[j];
    __syncthreads();

    size_t gb = (size_t)row * Tt;
    // write xh/xl, 8 bf16 packed per 16B store
    for (int g = tid; g < Tt / 8; g += 256) {
        int base = g * 8;
        uint4 ph, pl;
        unsigned short* hp = (unsigned short*)&ph;
        unsigned short* lp = (unsigned short*)&pl;
        #pragma unroll
        for (int k = 0; k < 8; k++) {
            __nv_bfloat16 h, l;
            split_bf16(xs[base + k], h, l);
            hp[k] = __bfloat16_as_ushort(h); lp[k] = __bfloat16_as_ushort(l);
        }
        *(uint4*)(g_xh + gb + base) = ph;
        *(uint4*)(g_xl + gb + base) = pl;
    }

    int base = tid * 16;
    float s1 = 0.f, s2 = 0.f;
    #pragma unroll
    for (int k = 0; k < 16; k++) {
        int t = base + k;
        float v = (t < len) ? xs[t] : 0.f;
        s1 += v; s2 += v * v;
    }
    // exclusive prefixes (internal barriers also fence the xh/xl reads above)
    block_exscan2(s1, s2, tid, ws1, ws2);

    float p1 = s1, p2 = s2;
    #pragma unroll
    for (int k = 0; k < 16; k++) {
        int t = base + k;
        float xv = xs[t];
        float v  = (t < len) ? xv : 0.f;
        p1 += v; p2 += v * v;
        int cn = min(t + 1, len); if (cn < 1) cn = 1;
        float rc  = __fdividef(1.f, (float)cn);
        float m   = p1 * rc;
        float var = p2 * rc - m * m;
        xs[t] = m;
        ss[t] = fast_sqrt(fmaxf(var, EPSF));
    }
    __syncthreads();

    for (int g = tid; g < Tt / 8; g += 256) {
        int bb = g * 8;
        uint4 mh, ml, sh, sl;
        unsigned short* mhp = (unsigned short*)&mh; unsigned short* mlp = (unsigned short*)&ml;
        unsigned short* shp = (unsigned short*)&sh; unsigned short* slp = (unsigned short*)&sl;
        #pragma unroll
        for (int k = 0; k < 8; k++) {
            __nv_bfloat16 h, l;
            split_bf16(xs[bb + k], h, l); mhp[k] = __bfloat16_as_ushort(h); mlp[k] = __bfloat16_as_ushort(l);
            split_bf16(ss[bb + k], h, l); shp[k] = __bfloat16_as_ushort(h); slp[k] = __bfloat16_as_ushort(l);
        }
        *(uint4*)(g_mh + gb + bb) = mh; *(uint4*)(g_ml + gb + bb) = ml;
        *(uint4*)(g_sh + gb + bb) = sh; *(uint4*)(g_sl + gb + bb) = sl;
    }
}

// ---------------- K2: double-buffered bf16 mma.sync GEMM (512 thr) + tanh + W2 reduce ----------------
#define BM 128
#define BK 32
#define NK (K3C / BK)        // 144
#define APITCH 272           // bytes per k-row (128 t * 2B + 16 pad)
#define BPITCH 80            // bytes per a-row (32 k * 2B + 16 pad)
#define OFF_AL 8704
#define OFF_BH 17408
#define OFF_BL 27648
#define SSTR   37888         // one stage: Ah+Al+Bh+Bl
#define OFF_RED (2 * SSTR)   // 75776
#define SMEM_GEMM (OFF_RED + 4 * BM * 4)    // 77824 B

struct StageRegs { uint4 ah, al, bh, bl; };

__device__ __forceinline__ StageRegs gemm_ldg(int j, int b, int t0, int tid) {
    int k0 = j * BK;
    int region = k0 / Cc;                // 0:x 1:mean 2:std (BK=32 never straddles)
    int cb = k0 - region * Cc;
    const __nv_bfloat16* pH = (region == 0 ? g_xh : (region == 1 ? g_mh : g_sh))
                              + ((size_t)(b * Cc + cb)) * Tt + t0;
    const __nv_bfloat16* pL = (region == 0 ? g_xl : (region == 1 ? g_ml : g_sl))
                              + ((size_t)(b * Cc + cb)) * Tt + t0;
    StageRegs s;
    int r  = tid >> 4, c  = tid & 15;    // A: 32 k-rows x 16 chunks(16B)
    s.ah = *(const uint4*)(pH + (size_t)r * Tt + c * 8);
    s.al = *(const uint4*)(pL + (size_t)r * Tt + c * 8);
    int rb = tid >> 2, cc = tid & 3;     // B: 128 a-rows x 4 chunks(16B)
    s.bh = *(const uint4*)(g_W1h + (size_t)rb * K3C + k0 + cc * 8);
    s.bl = *(const uint4*)(g_W1l + (size_t)rb * K3C + k0 + cc * 8);
    return s;
}

__device__ __forceinline__ void gemm_sts(char* st, const StageRegs& s, int tid) {
    int r  = tid >> 4, c  = tid & 15;
    *(uint4*)(st + r * APITCH + c * 16)           = s.ah;
    *(uint4*)(st + OFF_AL + r * APITCH + c * 16)  = s.al;
    int rb = tid >> 2, cc = tid & 3;
    *(uint4*)(st + OFF_BH + rb * BPITCH + cc * 16) = s.bh;
    *(uint4*)(st + OFF_BL + rb * BPITCH + cc * 16) = s.bl;
}

__global__ __launch_bounds__(512) void k_gemm_mma(const float* __restrict__ b1,
                                                  const float* __restrict__ W2) {
    extern __shared__ __align__(16) char dsm[];
    uint32_t sb = smem_u32(dsm);

    int tid = threadIdx.x;
    int wid = tid >> 5, lid = tid & 31;
    int wm = wid & 3;          // 4 m-groups * 32 t
    int wn = wid >> 2;         // 4 n-groups * 32 a
    int b  = blockIdx.y, t0 = blockIdx.x * BM;

    // ldmatrix lane addressing
    int a_row_off = (lid & 7) + ((lid >> 4) << 3);
    int a_t_off   = wm * 32 + ((lid >> 3) & 1) * 8;
    int b_row     = wn * 32 + (lid & 7) + ((lid >> 4) << 3);
    int b_k_off   = ((lid >> 3) & 1) * 8;

    float acc[2][4][4];      // [mf t-frag][nb 8a group][frag]
    #pragma unroll
    for (int i = 0; i < 2; i++)
        #pragma unroll
        for (int j = 0; j < 4; j++)
            #pragma unroll
            for (int q = 0; q < 4; q++) acc[i][j][q] = 0.f;

    // prologue: tile 0 -> regs -> smem buf0
    StageRegs sr = gemm_ldg(0, b, t0, tid);
    gemm_sts(dsm, sr, tid);
    __syncthreads();

    for (int it = 0; it < NK; it++) {
        bool has_next = (it + 1) < NK;
        if (has_next) sr = gemm_ldg(it + 1, b, t0, tid);

        uint32_t stb = sb + (it & 1) * SSTR;
        uint32_t uAh = stb, uAl = stb + OFF_AL, uBh = stb + OFF_BH, uBl = stb + OFF_BL;

        #pragma unroll
        for (int s = 0; s < 2; s++) {                 // two k16 steps
            uint32_t ah[2][4], al[2][4];
            #pragma unroll
            for (int mf = 0; mf < 2; mf++) {
                uint32_t addr = (s * 16 + a_row_off) * APITCH + (a_t_off + mf * 16) * 2;
                ldsm_x4_t(ah[mf][0], ah[mf][1], ah[mf][2], ah[mf][3], uAh + addr);
                ldsm_x4_t(al[mf][0], al[mf][1], al[mf][2], al[mf][3], uAl + addr);
            }
            #pragma unroll
            for (int nb2 = 0; nb2 < 2; nb2++) {       // 2 groups of 16 a
                uint32_t addr = (b_row + nb2 * 16) * BPITCH + (s * 16 + b_k_off) * 2;
                uint32_t bh[4], bl[4];
                ldsm_x4(bh[0], bh[1], bh[2], bh[3], uBh + addr);
                ldsm_x4(bl[0], bl[1], bl[2], bl[3], uBl + addr);
                #pragma unroll
                for (int half = 0; half < 2; half++) {
                    int nb = nb2 * 2 + half;
                    #pragma unroll
                    for (int mf = 0; mf < 2; mf++) {
                        mma_bf16(acc[mf][nb], ah[mf], bh + half * 2);
                        mma_bf16(acc[mf][nb], al[mf], bh + half * 2);
                        mma_bf16(acc[mf][nb], ah[mf], bl + half * 2);
                    }
                }
            }
        }
        // write next tile into the other buffer (not read by this iteration)
        if (has_next) gemm_sts(dsm + ((it + 1) & 1) * SSTR, sr, tid);
        __syncthreads();
    }

    // ---- epilogue: h = tanh(acc + b1[a]); row-sum of W2[a]*h over a ----
    float* red = (float*)(dsm + OFF_RED);   // [4][BM]
    float rs[2][2] = {{0.f, 0.f}, {0.f, 0.f}};
    #pragma unroll
    for (int nb = 0; nb < 4; nb++) {
        int a0 = wn * 32 + nb * 8 + (lid & 3) * 2;
        float w20 = __ldg(&W2[a0]),   w21 = __ldg(&W2[a0 + 1]);
        float b10 = __ldg(&b1[a0]),   b11 = __ldg(&b1[a0 + 1]);
        #pragma unroll
        for (int mf = 0; mf < 2; mf++) {
            rs[mf][0] += w20 * fast_tanh(acc[mf][nb][0] + b10)
                       + w21 * fast_tanh(acc[mf][nb][1] + b11);
            rs[mf][1] += w20 * fast_tanh(acc[mf][nb][2] + b10)
                       + w21 * fast_tanh(acc[mf][nb][3] + b11);
        }
    }
    #pragma unroll
    for (int mf = 0; mf < 2; mf++)
        #pragma unroll
        for (int r = 0; r < 2; r++) {
            rs[mf][r] += __shfl_xor_sync(0xFFFFFFFF, rs[mf][r], 1);
            rs[mf][r] += __shfl_xor_sync(0xFFFFFFFF, rs[mf][r], 2);
        }
    if ((lid & 3) == 0) {
        int trow = wm * 32 + (lid >> 2);
        #pragma unroll
        for (int mf = 0; mf < 2; mf++) {
            red[wn * BM + trow + mf * 16]     = rs[mf][0];
            red[wn * BM + trow + mf * 16 + 8] = rs[mf][1];
        }
    }
    __syncthreads();
    if (tid < BM)
        g_logits[b * Tt + t0 + tid] = red[tid] + red[BM + tid] + red[2 * BM + tid] + red[3 * BM + tid];
}

// ---------------- K3: per-batch max, exp, cumsum -> e, Z, 1/Z ----------------
__global__ __launch_bounds__(256) void k_softmax() {
    int b = blockIdx.x;
    __shared__ float sm[Tt];
    __shared__ float red[256];
    __shared__ float ws[8];
    int tid = threadIdx.x;

    const float* lr = g_logits + b * Tt;
    float mx = -INFINITY;
    for (int j = tid; j < Tt; j += 256) { float v = lr[j]; sm[j] = v; mx = fmaxf(mx, v); }
    red[tid] = mx;
    __syncthreads();
    for (int off = 128; off; off >>= 1) {
        if (tid < off) red[tid] = fmaxf(red[tid], red[tid + off]);
        __syncthreads();
    }
    float M = red[0];
    __syncthreads();

    int base = tid * 16;
    float s = 0.f;
    #pragma unroll
    for (int k = 0; k < 16; k++) {
        float ev = __expf(sm[base + k] - M);
        sm[base + k] = ev;
        s += ev;
    }
    float p = block_exscan1(s, tid, ws);
    #pragma unroll
    for (int k = 0; k < 16; k++) {
        int t = base + k;
        float ev = sm[t];
        p += ev;
        g_e[b * Tt + t] = ev;
        g_Z[b * Tt + t] = p;
        g_Zi[b * Tt + t] = 1.0f / p;    // full-precision; this kernel is tiny
    }
}

// ---------------- K4: weighted mean/std scans + final reduction ----------------
__global__ __launch_bounds__(256) void k_weighted(const float* __restrict__ x,
                                                  float* __restrict__ out) {
    int row = blockIdx.x;
    int b = row / Cc;
    int c = row - b * Cc;

    __shared__ float xs[Tt];
    __shared__ float es[Tt];
    __shared__ float zis[Tt];
    __shared__ float ws[8];
    __shared__ float w1s[256], w2s[256];

    int tid = threadIdx.x;
    const float* xr = x + (size_t)row * Tt;
    const float* er = g_e + b * Tt;
    const float* zir = g_Zi + b * Tt;
    for (int j = tid; j < Tt; j += 256) { xs[j] = xr[j]; es[j] = er[j]; zis[j] = zir[j]; }
    __syncthreads();

    int base = tid * 16;

    float s = 0.f;
    #pragma unroll
    for (int k = 0; k < 16; k++) { int t = base + k; s += es[t] * xs[t]; }
    float p = block_exscan1(s, tid, ws);

    float sum_wm = 0.f, s2 = 0.f;
    #pragma unroll
    for (int k = 0; k < 16; k++) {
        int t = base + k;
        p += es[t] * xs[t];
        float wm = p * zis[t];
        sum_wm += wm;
        float d = xs[t] - wm;
        float v = es[t] * d * d;
        xs[t] = v;
        s2 += v;
    }
    __syncthreads();   // ws reuse fence

    float q = block_exscan1(s2, tid, ws);
    float sum_ws = 0.f;
    #pragma unroll
    for (int k = 0; k < 16; k++) {
        int t = base + k;
        q += xs[t];
        float wv = q * zis[t];
        sum_ws += fast_sqrt(fmaxf(wv, EPSF));
    }
    __syncthreads();

    w1s[tid] = sum_wm;
    w2s[tid] = sum_ws;
    __syncthreads();
    for (int off = 128; off; off >>= 1) {
        if (tid < off) { w1s[tid] += w1s[tid + off]; w2s[tid] += w2s[tid + off]; }
        __syncthreads();
    }
    if (tid == 0) {
        const float FW = (float)(1.0 / (4096.0 + 1e-12));
        out[(size_t)b * 2 * Cc + c]      = w1s[0] * FW;
        out[(size_t)b * 2 * Cc + Cc + c] = w2s[0] * FW;
    }
}

// ---------------- launch ----------------
extern "C" void kernel_launch(void* const* d_in, const int* in_sizes, int n_in,
                              void* d_out, int out_size) {
    (void)in_sizes; (void)n_in; (void)out_size;
    const float* x  = (const float*)d_in[0];
    const int*   L  = (const int*)  d_in[1];
    const float* W1 = (const float*)d_in[2];
    const float* b1 = (const float*)d_in[3];
    const float* W2 = (const float*)d_in[4];
    // d_in[5] = b2: constant shift on logits; cancels exactly in softmax.
    float* out = (float*)d_out;

    cudaFuncSetAttribute(k_gemm_mma, cudaFuncAttributeMaxDynamicSharedMemorySize, SMEM_GEMM);

    k_prepW<<<(Aa * K3C + 255) / 256, 256>>>(W1);
    k_marker<<<1, 32>>>();
    k_marker2<<<1, 32>>>();                    // k_scan_stats lands in ncu's captured slot
    k_scan_stats<<<Bb * Cc, 256>>>(x, L);
    dim3 g2(Tt / BM, Bb);
    k_gemm_mma<<<g2, 512, SMEM_GEMM>>>(b1, W2);
    k_softmax<<<Bb, 256>>>();
    k_weighted<<<Bb * Cc, 256>>>(x, out);
}

// round 14
// speedup vs baseline: 3.6086x; 2.0653x over previous
#include <cuda_runtime.h>
#include <cuda_bf16.h>
#include <cstdint>
#include <math.h>

// Problem constants
#define Bb   8
#define Cc   1536
#define Tt   4096
#define Aa   128
#define K3C  4608          // 3*C
#define EPSF 1e-12f

// ---------------- scratch (device globals; no allocation allowed) ----------------
__device__ __nv_bfloat16 g_xh[(size_t)Bb * Cc * Tt];   // x hi (96MB)
__device__ __nv_bfloat16 g_xl[(size_t)Bb * Cc * Tt];
__device__ __nv_bfloat16 g_mh[(size_t)Bb * Cc * Tt];   // mean hi
__device__ __nv_bfloat16 g_ml[(size_t)Bb * Cc * Tt];
__device__ __nv_bfloat16 g_sh[(size_t)Bb * Cc * Tt];   // std hi
__device__ __nv_bfloat16 g_sl[(size_t)Bb * Cc * Tt];
__device__ __nv_bfloat16 g_W1h[Aa * K3C];
__device__ __nv_bfloat16 g_W1l[Aa * K3C];
__device__ float g_logits[Bb * Tt];
__device__ float g_e     [Bb * Tt];
__device__ float g_Zi    [Bb * Tt];   // 1/Z, precomputed in K3

// ---------------- helpers ----------------
__device__ __forceinline__ uint32_t smem_u32(const void* p) {
    uint32_t a;
    asm("{ .reg .u64 t; cvta.to.shared.u64 t, %1; cvt.u32.u64 %0, t; }" : "=r"(a) : "l"(p));
    return a;
}
__device__ __forceinline__ int load_len(const int* __restrict__ L, int b) {
    return (L[1] == 0) ? L[2 * b] : L[b];   // int64 vs int32 detection
}
__device__ __forceinline__ void split_bf16(float v, __nv_bfloat16& h, __nv_bfloat16& l) {
    h = __float2bfloat16_rn(v);
    l = __float2bfloat16_rn(v - __bfloat162float(h));
}
__device__ __forceinline__ float fast_tanh(float v) {
    float e = __expf(2.f * v);          // inf-safe: e=inf -> 1, e=0 -> -1
    return 1.f - 2.f / (e + 1.f);
}
// fast sqrt for v >= EPSF: v * rsqrt(v)
__device__ __forceinline__ float fast_sqrt(float v) {
    return v * __frsqrt_rn(v);
}
__device__ __forceinline__ float warp_iscan(float v, int lane) {
    #pragma unroll
    for (int off = 1; off < 32; off <<= 1) {
        float n = __shfl_up_sync(0xFFFFFFFFu, v, off);
        if (lane >= off) v += n;
    }
    return v;
}
// block-wide (256 thr) EXCLUSIVE scan of two values; 2 barriers.
__device__ __forceinline__ void block_exscan2(float& v1, float& v2, int tid,
                                              float* ws1, float* ws2) {
    int lane = tid & 31, wid = tid >> 5;
    float o1 = v1, o2 = v2;
    float i1 = warp_iscan(o1, lane), i2 = warp_iscan(o2, lane);
    if (lane == 31) { ws1[wid] = i1; ws2[wid] = i2; }
    __syncthreads();
    if (wid == 0) {
        float a1 = (lane < 8) ? ws1[lane] : 0.f;
        float a2 = (lane < 8) ? ws2[lane] : 0.f;
        float c1 = warp_iscan(a1, lane), c2 = warp_iscan(a2, lane);
        if (lane < 8) { ws1[lane] = c1; ws2[lane] = c2; }
    }
    __syncthreads();
    float p1 = wid ? ws1[wid - 1] : 0.f;
    float p2 = wid ? ws2[wid - 1] : 0.f;
    v1 = p1 + i1 - o1;
    v2 = p2 + i2 - o2;
}
__device__ __forceinline__ float block_exscan1(float v, int tid, float* ws) {
    int lane = tid & 31, wid = tid >> 5;
    float o = v;
    float i = warp_iscan(o, lane);
    if (lane == 31) ws[wid] = i;
    __syncthreads();
    if (wid == 0) {
        float a = (lane < 8) ? ws[lane] : 0.f;
        float c = warp_iscan(a, lane);
        if (lane < 8) ws[lane] = c;
    }
    __syncthreads();
    float p = wid ? ws[wid - 1] : 0.f;
    return p + i - o;
}

// ldmatrix / mma wrappers
__device__ __forceinline__ void ldsm_x4(uint32_t& r0, uint32_t& r1, uint32_t& r2, uint32_t& r3, uint32_t a) {
    asm volatile("ldmatrix.sync.aligned.m8n8.x4.shared.b16 {%0,%1,%2,%3}, [%4];"
                 : "=r"(r0), "=r"(r1), "=r"(r2), "=r"(r3) : "r"(a));
}
__device__ __forceinline__ void ldsm_x4_t(uint32_t& r0, uint32_t& r1, uint32_t& r2, uint32_t& r3, uint32_t a) {
    asm volatile("ldmatrix.sync.aligned.m8n8.x4.trans.shared.b16 {%0,%1,%2,%3}, [%4];"
                 : "=r"(r0), "=r"(r1), "=r"(r2), "=r"(r3) : "r"(a));
}
__device__ __forceinline__ void mma_bf16(float* d, const uint32_t* a, const uint32_t* b) {
    asm volatile(
        "mma.sync.aligned.m16n8k16.row.col.f32.bf16.bf16.f32 "
        "{%0,%1,%2,%3},{%4,%5,%6,%7},{%8,%9},{%0,%1,%2,%3};"
        : "+f"(d[0]), "+f"(d[1]), "+f"(d[2]), "+f"(d[3])
        : "r"(a[0]), "r"(a[1]), "r"(a[2]), "r"(a[3]), "r"(b[0]), "r"(b[1]));
}

// ---------------- K0: W1 -> bf16 hi/lo ----------------
__global__ __launch_bounds__(256) void k_prepW(const float* __restrict__ W1) {
    int i = blockIdx.x * 256 + threadIdx.x;
    if (i < Aa * K3C) {
        __nv_bfloat16 h, l;
        split_bf16(W1[i], h, l);
        g_W1h[i] = h; g_W1l[i] = l;
    }
}

// ---------------- markers: align ncu's captured 4th slot onto k_scan_stats ----------------
__global__ void k_marker() {}
__global__ void k_marker2() {}

// ---------------- K1: register-resident causal scan; x/mean/std -> bf16 hi/lo ----------------
__global__ __launch_bounds__(256) void k_scan_stats(const float* __restrict__ x,
                                                    const int* __restrict__ L) {
    int row = blockIdx.x;               // b*C + c
    int b = row / Cc;
    int len = load_len(L, b);

    __shared__ float ws1[8], ws2[8];

    int tid = threadIdx.x;
    int base = tid * 16;
    const float* xr = x + (size_t)row * Tt + base;

    float xv[16];
    #pragma unroll
    for (int i = 0; i < 4; i++) {
        float4 v = *(const float4*)(xr + i * 4);
        xv[i * 4 + 0] = v.x; xv[i * 4 + 1] = v.y; xv[i * 4 + 2] = v.z; xv[i * 4 + 3] = v.w;
    }

    size_t gb = (size_t)row * Tt + base;
    // pack + store xh/xl (reg -> global, no smem)
    {
        uint32_t xhp[8], xlp[8];
        #pragma unroll
        for (int k2 = 0; k2 < 8; k2++) {
            __nv_bfloat16 h0, l0, h1, l1;
            split_bf16(xv[2 * k2],     h0, l0);
            split_bf16(xv[2 * k2 + 1], h1, l1);
            xhp[k2] = (uint32_t)__bfloat16_as_ushort(h0) | ((uint32_t)__bfloat16_as_ushort(h1) << 16);
            xlp[k2] = (uint32_t)__bfloat16_as_ushort(l0) | ((uint32_t)__bfloat16_as_ushort(l1) << 16);
        }
        *(uint4*)(g_xh + gb)     = make_uint4(xhp[0], xhp[1], xhp[2], xhp[3]);
        *(uint4*)(g_xh + gb + 8) = make_uint4(xhp[4], xhp[5], xhp[6], xhp[7]);
        *(uint4*)(g_xl + gb)     = make_uint4(xlp[0], xlp[1], xlp[2], xlp[3]);
        *(uint4*)(g_xl + gb + 8) = make_uint4(xlp[4], xlp[5], xlp[6], xlp[7]);
    }

    float s1 = 0.f, s2 = 0.f;
    #pragma unroll
    for (int k = 0; k < 16; k++) {
        float v = (base + k < len) ? xv[k] : 0.f;
        s1 += v; s2 += v * v;
    }
    block_exscan2(s1, s2, tid, ws1, ws2);   // exclusive prefixes

    float p1 = s1, p2 = s2;
    uint32_t mhp[8], mlp[8], shp[8], slp[8];
    #pragma unroll
    for (int k = 0; k < 16; k++) {
        float v = (base + k < len) ? xv[k] : 0.f;
        p1 += v; p2 += v * v;
        int cn = min(base + k + 1, len);
        float rc  = __fdividef(1.f, (float)cn);
        float m   = p1 * rc;
        float var = p2 * rc - m * m;
        float sd  = fast_sqrt(fmaxf(var, EPSF));
        __nv_bfloat16 h, l;
        split_bf16(m, h, l);
        uint32_t mh16 = __bfloat16_as_ushort(h), ml16 = __bfloat16_as_ushort(l);
        split_bf16(sd, h, l);
        uint32_t sh16 = __bfloat16_as_ushort(h), sl16 = __bfloat16_as_ushort(l);
        int k2 = k >> 1, sh = (k & 1) << 4;
        if ((k & 1) == 0) { mhp[k2] = mh16; mlp[k2] = ml16; shp[k2] = sh16; slp[k2] = sl16; }
        else { mhp[k2] |= mh16 << sh; mlp[k2] |= ml16 << sh; shp[k2] |= sh16 << sh; slp[k2] |= sl16 << sh; }
    }
    *(uint4*)(g_mh + gb)     = make_uint4(mhp[0], mhp[1], mhp[2], mhp[3]);
    *(uint4*)(g_mh + gb + 8) = make_uint4(mhp[4], mhp[5], mhp[6], mhp[7]);
    *(uint4*)(g_ml + gb)     = make_uint4(mlp[0], mlp[1], mlp[2], mlp[3]);
    *(uint4*)(g_ml + gb + 8) = make_uint4(mlp[4], mlp[5], mlp[6], mlp[7]);
    *(uint4*)(g_sh + gb)     = make_uint4(shp[0], shp[1], shp[2], shp[3]);
    *(uint4*)(g_sh + gb + 8) = make_uint4(shp[4], shp[5], shp[6], shp[7]);
    *(uint4*)(g_sl + gb)     = make_uint4(slp[0], slp[1], slp[2], slp[3]);
    *(uint4*)(g_sl + gb + 8) = make_uint4(slp[4], slp[5], slp[6], slp[7]);
}

// ---------------- K2: double-buffered bf16 mma.sync GEMM (512 thr) + tanh + W2 reduce ----------------
#define BM 128
#define BK 32
#define NK (K3C / BK)        // 144
#define APITCH 272           // bytes per k-row (128 t * 2B + 16 pad)
#define BPITCH 80            // bytes per a-row (32 k * 2B + 16 pad)
#define OFF_AL 8704
#define OFF_BH 17408
#define OFF_BL 27648
#define SSTR   37888         // one stage: Ah+Al+Bh+Bl
#define OFF_RED (2 * SSTR)   // 75776
#define SMEM_GEMM (OFF_RED + 4 * BM * 4)    // 77824 B

struct StageRegs { uint4 ah, al, bh, bl; };

__device__ __forceinline__ StageRegs gemm_ldg(int j, int b, int t0, int tid) {
    int k0 = j * BK;
    int region = k0 / Cc;                // 0:x 1:mean 2:std (BK=32 never straddles)
    int cb = k0 - region * Cc;
    const __nv_bfloat16* pH = (region == 0 ? g_xh : (region == 1 ? g_mh : g_sh))
                              + ((size_t)(b * Cc + cb)) * Tt + t0;
    const __nv_bfloat16* pL = (region == 0 ? g_xl : (region == 1 ? g_ml : g_sl))
                              + ((size_t)(b * Cc + cb)) * Tt + t0;
    StageRegs s;
    int r  = tid >> 4, c  = tid & 15;    // A: 32 k-rows x 16 chunks(16B)
    s.ah = *(const uint4*)(pH + (size_t)r * Tt + c * 8);
    s.al = *(const uint4*)(pL + (size_t)r * Tt + c * 8);
    int rb = tid >> 2, cc = tid & 3;     // B: 128 a-rows x 4 chunks(16B)
    s.bh = *(const uint4*)(g_W1h + (size_t)rb * K3C + k0 + cc * 8);
    s.bl = *(const uint4*)(g_W1l + (size_t)rb * K3C + k0 + cc * 8);
    return s;
}

__device__ __forceinline__ void gemm_sts(char* st, const StageRegs& s, int tid) {
    int r  = tid >> 4, c  = tid & 15;
    *(uint4*)(st + r * APITCH + c * 16)           = s.ah;
    *(uint4*)(st + OFF_AL + r * APITCH + c * 16)  = s.al;
    int rb = tid >> 2, cc = tid & 3;
    *(uint4*)(st + OFF_BH + rb * BPITCH + cc * 16) = s.bh;
    *(uint4*)(st + OFF_BL + rb * BPITCH + cc * 16) = s.bl;
}

__global__ __launch_bounds__(512) void k_gemm_mma(const float* __restrict__ b1,
                                                  const float* __restrict__ W2) {
    extern __shared__ __align__(16) char dsm[];
    uint32_t sb = smem_u32(dsm);

    int tid = threadIdx.x;
    int wid = tid >> 5, lid = tid & 31;
    int wm = wid & 3;          // 4 m-groups * 32 t
    int wn = wid >> 2;         // 4 n-groups * 32 a
    int b  = blockIdx.y, t0 = blockIdx.x * BM;

    // ldmatrix lane addressing
    int a_row_off = (lid & 7) + ((lid >> 4) << 3);
    int a_t_off   = wm * 32 + ((lid >> 3) & 1) * 8;
    int b_row     = wn * 32 + (lid & 7) + ((lid >> 4) << 3);
    int b_k_off   = ((lid >> 3) & 1) * 8;

    float acc[2][4][4];      // [mf t-frag][nb 8a group][frag]
    #pragma unroll
    for (int i = 0; i < 2; i++)
        #pragma unroll
        for (int j = 0; j < 4; j++)
            #pragma unroll
            for (int q = 0; q < 4; q++) acc[i][j][q] = 0.f;

    // prologue: tile 0 -> regs -> smem buf0
    StageRegs sr = gemm_ldg(0, b, t0, tid);
    gemm_sts(dsm, sr, tid);
    __syncthreads();

    for (int it = 0; it < NK; it++) {
        bool has_next = (it + 1) < NK;
        if (has_next) sr = gemm_ldg(it + 1, b, t0, tid);

        uint32_t stb = sb + (it & 1) * SSTR;
        uint32_t uAh = stb, uAl = stb + OFF_AL, uBh = stb + OFF_BH, uBl = stb + OFF_BL;

        #pragma unroll
        for (int s = 0; s < 2; s++) {                 // two k16 steps
            uint32_t ah[2][4], al[2][4];
            #pragma unroll
            for (int mf = 0; mf < 2; mf++) {
                uint32_t addr = (s * 16 + a_row_off) * APITCH + (a_t_off + mf * 16) * 2;
                ldsm_x4_t(ah[mf][0], ah[mf][1], ah[mf][2], ah[mf][3], uAh + addr);
                ldsm_x4_t(al[mf][0], al[mf][1], al[mf][2], al[mf][3], uAl + addr);
            }
            #pragma unroll
            for (int nb2 = 0; nb2 < 2; nb2++) {       // 2 groups of 16 a
                uint32_t addr = (b_row + nb2 * 16) * BPITCH + (s * 16 + b_k_off) * 2;
                uint32_t bh[4], bl[4];
                ldsm_x4(bh[0], bh[1], bh[2], bh[3], uBh + addr);
                ldsm_x4(bl[0], bl[1], bl[2], bl[3], uBl + addr);
                #pragma unroll
                for (int half = 0; half < 2; half++) {
                    int nb = nb2 * 2 + half;
                    #pragma unroll
                    for (int mf = 0; mf < 2; mf++) {
                        mma_bf16(acc[mf][nb], ah[mf], bh + half * 2);
                        mma_bf16(acc[mf][nb], al[mf], bh + half * 2);
                        mma_bf16(acc[mf][nb], ah[mf], bl + half * 2);
                    }
                }
            }
        }
        // write next tile into the other buffer (not read by this iteration)
        if (has_next) gemm_sts(dsm + ((it + 1) & 1) * SSTR, sr, tid);
        __syncthreads();
    }

    // ---- epilogue: h = tanh(acc + b1[a]); row-sum of W2[a]*h over a ----
    float* red = (float*)(dsm + OFF_RED);   // [4][BM]
    float rs[2][2] = {{0.f, 0.f}, {0.f, 0.f}};
    #pragma unroll
    for (int nb = 0; nb < 4; nb++) {
        int a0 = wn * 32 + nb * 8 + (lid & 3) * 2;
        float w20 = __ldg(&W2[a0]),   w21 = __ldg(&W2[a0 + 1]);
        float b10 = __ldg(&b1[a0]),   b11 = __ldg(&b1[a0 + 1]);
        #pragma unroll
        for (int mf = 0; mf < 2; mf++) {
            rs[mf][0] += w20 * fast_tanh(acc[mf][nb][0] + b10)
                       + w21 * fast_tanh(acc[mf][nb][1] + b11);
            rs[mf][1] += w20 * fast_tanh(acc[mf][nb][2] + b10)
                       + w21 * fast_tanh(acc[mf][nb][3] + b11);
        }
    }
    #pragma unroll
    for (int mf = 0; mf < 2; mf++)
        #pragma unroll
        for (int r = 0; r < 2; r++) {
            rs[mf][r] += __shfl_xor_sync(0xFFFFFFFF, rs[mf][r], 1);
            rs[mf][r] += __shfl_xor_sync(0xFFFFFFFF, rs[mf][r], 2);
        }
    if ((lid & 3) == 0) {
        int trow = wm * 32 + (lid >> 2);
        #pragma unroll
        for (int mf = 0; mf < 2; mf++) {
            red[wn * BM + trow + mf * 16]     = rs[mf][0];
            red[wn * BM + trow + mf * 16 + 8] = rs[mf][1];
        }
    }
    __syncthreads();
    if (tid < BM)
        g_logits[b * Tt + t0 + tid] = red[tid] + red[BM + tid] + red[2 * BM + tid] + red[3 * BM + tid];
}

// ---------------- K3: per-batch max, exp, cumsum -> e, 1/Z ----------------
__global__ __launch_bounds__(256) void k_softmax() {
    int b = blockIdx.x;
    __shared__ float sm[Tt];
    __shared__ float red[256];
    __shared__ float ws[8];
    int tid = threadIdx.x;

    const float* lr = g_logits + b * Tt;
    float mx = -INFINITY;
    for (int j = tid; j < Tt; j += 256) { float v = lr[j]; sm[j] = v; mx = fmaxf(mx, v); }
    red[tid] = mx;
    __syncthreads();
    for (int off = 128; off; off >>= 1) {
        if (tid < off) red[tid] = fmaxf(red[tid], red[tid + off]);
        __syncthreads();
    }
    float M = red[0];
    __syncthreads();

    int base = tid * 16;
    float s = 0.f;
    #pragma unroll
    for (int k = 0; k < 16; k++) {
        float ev = __expf(sm[base + k] - M);
        sm[base + k] = ev;
        s += ev;
    }
    float p = block_exscan1(s, tid, ws);
    #pragma unroll
    for (int k = 0; k < 16; k++) {
        int t = base + k;
        float ev = sm[t];
        p += ev;
        g_e[b * Tt + t] = ev;
        g_Zi[b * Tt + t] = 1.0f / p;    // full-precision; this kernel is tiny
    }
}

// ---------------- K4: register-resident weighted mean/std scans + final reduction ----------------
__global__ __launch_bounds__(256) void k_weighted(const float* __restrict__ x,
                                                  float* __restrict__ out) {
    int row = blockIdx.x;
    int b = row / Cc;
    int c = row - b * Cc;

    __shared__ float ws[8];
    __shared__ float r1[8], r2[8];

    int tid = threadIdx.x;
    int base = tid * 16;
    const float* xr  = x    + (size_t)row * Tt + base;
    const float* er  = g_e  + b * Tt + base;
    const float* zir = g_Zi + b * Tt + base;

    float xv[16], ev[16], ziv[16];
    #pragma unroll
    for (int i = 0; i < 4; i++) {
        float4 v = *(const float4*)(xr + i * 4);
        xv[i*4+0] = v.x; xv[i*4+1] = v.y; xv[i*4+2] = v.z; xv[i*4+3] = v.w;
        float4 e = *(const float4*)(er + i * 4);
        ev[i*4+0] = e.x; ev[i*4+1] = e.y; ev[i*4+2] = e.z; ev[i*4+3] = e.w;
        float4 z = *(const float4*)(zir + i * 4);
        ziv[i*4+0] = z.x; ziv[i*4+1] = z.y; ziv[i*4+2] = z.z; ziv[i*4+3] = z.w;
    }

    float s = 0.f;
    #pragma unroll
    for (int k = 0; k < 16; k++) s += ev[k] * xv[k];
    float p = block_exscan1(s, tid, ws);

    float sum_wm = 0.f, s2 = 0.f;
    #pragma unroll
    for (int k = 0; k < 16; k++) {
        p += ev[k] * xv[k];
        float wm = p * ziv[k];
        sum_wm += wm;
        float d = xv[k] - wm;
        float v = ev[k] * d * d;
        xv[k] = v;                   // reuse regs for second scan
        s2 += v;
    }
    __syncthreads();   // ws reuse fence

    float q = block_exscan1(s2, tid, ws);
    float sum_ws = 0.f;
    #pragma unroll
    for (int k = 0; k < 16; k++) {
        q += xv[k];
        sum_ws += fast_sqrt(fmaxf(q * ziv[k], EPSF));
    }

    // block reduction of the two sums
    int lane = tid & 31, w = tid >> 5;
    #pragma unroll
    for (int off = 16; off; off >>= 1) {
        sum_wm += __shfl_xor_sync(0xFFFFFFFFu, sum_wm, off);
        sum_ws += __shfl_xor_sync(0xFFFFFFFFu, sum_ws, off);
    }
    if (lane == 0) { r1[w] = sum_wm; r2[w] = sum_ws; }
    __syncthreads();
    if (tid == 0) {
        float a1 = 0.f, a2 = 0.f;
        #pragma unroll
        for (int i = 0; i < 8; i++) { a1 += r1[i]; a2 += r2[i]; }
        const float FW = (float)(1.0 / (4096.0 + 1e-12));
        out[(size_t)b * 2 * Cc + c]      = a1 * FW;
        out[(size_t)b * 2 * Cc + Cc + c] = a2 * FW;
    }
}

// ---------------- launch ----------------
extern "C" void kernel_launch(void* const* d_in, const int* in_sizes, int n_in,
                              void* d_out, int out_size) {
    (void)in_sizes; (void)n_in; (void)out_size;
    const float* x  = (const float*)d_in[0];
    const int*   L  = (const int*)  d_in[1];
    const float* W1 = (const float*)d_in[2];
    const float* b1 = (const float*)d_in[3];
    const float* W2 = (const float*)d_in[4];
    // d_in[5] = b2: constant shift on logits; cancels exactly in softmax.
    float* out = (float*)d_out;

    cudaFuncSetAttribute(k_gemm_mma, cudaFuncAttributeMaxDynamicSharedMemorySize, SMEM_GEMM);

    k_prepW<<<(Aa * K3C + 255) / 256, 256>>>(W1);
    k_marker<<<1, 32>>>();
    k_marker2<<<1, 32>>>();                    // new k_scan_stats lands in ncu's captured slot
    k_scan_stats<<<Bb * Cc, 256>>>(x, L);
    dim3 g2(Tt / BM, Bb);
    k_gemm_mma<<<g2, 512, SMEM_GEMM>>>(b1, W2);
    k_softmax<<<Bb, 256>>>();
    k_weighted<<<Bb * Cc, 256>>>(x, out);
}